// round 12
// baseline (speedup 1.0000x reference)
#include <cuda_runtime.h>
#include <cuda_bf16.h>
#include <cstdint>
#include <cstddef>

// ---------------- problem constants ----------------
#define NN     50000
#define EE     500000
#define NPG    6250
#define NB     8
#define FSTR   272
// internal feats layout per node: [h0(64) h1(64) h2(64) h3(64) feat(10) pad(6)]

// ---------------- device scratch ----------------
__device__ __align__(16) float g_h     [NN * 64];
__device__ __align__(16) float g_hni   [NN * 128];
__device__ __align__(16) float g_hnj   [NN * 128];
__device__ __align__(16) float g_hnode [NN * 128];
__device__ __align__(16) float g_hatt  [NN * 128];
__device__ __align__(16) float g_feats [NN * FSTR];
__device__ __align__(16) float g_e     [EE * 2];
__device__ int   g_deg   [NN];
__device__ int   g_rowptr[NN + 1];
__device__ int   g_cursor[NN];
__device__ int   g_eidx  [EE];
__device__ int   g_bsum  [256];
__device__ __align__(16) float g_table [217 * 128];
__device__ __align__(16) float g_crcrp [5 * 128];
__device__ __align__(16) float g_gmax  [NB * FSTR];

// ---------------- feature-encoder MLP (feat -> h0) ----------------
__global__ __launch_bounds__(256) void fe_mlp_k(
    const float* __restrict__ feat, const float* __restrict__ W0,
    const float* __restrict__ b0,   const float* __restrict__ W1,
    const float* __restrict__ b1,   float* __restrict__ h,
    float* __restrict__ feats)
{
    __shared__ float sW0[640], sb0[64], sW1[4096], sb1[64];
    int tid = threadIdx.x;
    for (int i = tid; i < 640;  i += 256) sW0[i] = W0[i];
    for (int i = tid; i < 4096; i += 256) sW1[i] = W1[i];
    if (tid < 64) { sb0[tid] = b0[tid]; sb1[tid] = b1[tid]; }
    __syncthreads();
    int n = blockIdx.x * 256 + tid;
    if (n >= NN) return;
    float f[10];
#pragma unroll
    for (int i = 0; i < 10; i++) {
        f[i] = feat[n * 10 + i];
        feats[(size_t)n * FSTR + 256 + i] = f[i];
    }
    float hid[64];
#pragma unroll
    for (int c = 0; c < 64; c++) {
        float s = sb0[c];
#pragma unroll
        for (int k = 0; k < 10; k++) s += f[k] * sW0[k * 64 + c];
        hid[c] = fmaxf(s, 0.f);
    }
    for (int c = 0; c < 64; c++) {
        float s = sb1[c];
#pragma unroll
        for (int k = 0; k < 64; k++) s += hid[k] * sW1[k * 64 + c];
        h[(size_t)n * 64 + c] = s;
        feats[(size_t)n * FSTR + c] = s;
    }
}

// ---------------- CSR build ----------------
__global__ void zero_int_k(int* p, int n) {
    int i = blockIdx.x * 256 + threadIdx.x;
    if (i < n) p[i] = 0;
}
__global__ void hist_k(const int* __restrict__ dst, int* deg) {
    int e = blockIdx.x * 256 + threadIdx.x;
    if (e < EE) atomicAdd(&deg[dst[e]], 1);
}
__global__ void scan_partial_k(const int* __restrict__ deg, int* bsum) {
    __shared__ int s[256];
    int i = blockIdx.x * 256 + threadIdx.x;
    s[threadIdx.x] = (i < NN) ? deg[i] : 0;
    __syncthreads();
#pragma unroll
    for (int o = 128; o; o >>= 1) {
        if (threadIdx.x < o) s[threadIdx.x] += s[threadIdx.x + o];
        __syncthreads();
    }
    if (threadIdx.x == 0) bsum[blockIdx.x] = s[0];
}
__global__ void scan_bsum_k(int* bsum, int nb) {
    __shared__ int s[256];
    int t = threadIdx.x;
    int v = (t < nb) ? bsum[t] : 0;
    s[t] = v;
    __syncthreads();
#pragma unroll
    for (int o = 1; o < 256; o <<= 1) {
        int x = (t >= o) ? s[t - o] : 0;
        __syncthreads();
        s[t] += x;
        __syncthreads();
    }
    if (t < nb) bsum[t] = s[t] - v;   // exclusive
}
__global__ void scan_final_k(const int* __restrict__ deg, const int* __restrict__ bsum,
                             int* rowptr, int* cursor) {
    __shared__ int s[256];
    int i = blockIdx.x * 256 + threadIdx.x;
    int v = (i < NN) ? deg[i] : 0;
    s[threadIdx.x] = v;
    __syncthreads();
#pragma unroll
    for (int o = 1; o < 256; o <<= 1) {
        int x = (threadIdx.x >= o) ? s[threadIdx.x - o] : 0;
        __syncthreads();
        s[threadIdx.x] += x;
        __syncthreads();
    }
    if (i < NN) {
        int off = bsum[blockIdx.x] + s[threadIdx.x] - v;
        rowptr[i] = off;
        cursor[i] = off;
    }
    if (i == NN - 1) rowptr[NN] = EE;
}
__global__ void scatter_k(const int* __restrict__ dst, int* cursor, int* eidx) {
    int e = blockIdx.x * 256 + threadIdx.x;
    if (e < EE) {
        int pos = atomicAdd(&cursor[dst[e]], 1);
        eidx[pos] = e;
    }
}

// ---------------- per-layer f_fij precompute ----------------
__global__ void precompute_fij_k(
    const float* __restrict__ etype_emb, const float* __restrict__ rid_emb,
    const float* __restrict__ rc_W, const float* __restrict__ rp_W,
    const float* __restrict__ rc_b, const float* __restrict__ rp_b,
    const float* __restrict__ Wf,   const float* __restrict__ ebias,
    float* __restrict__ table, float* __restrict__ crcrp)
{
    int row = blockIdx.x;         // 0..221
    int c   = threadIdx.x;        // 0..127
    __shared__ float v[64];
    if (threadIdx.x < 64) {
        int k = threadIdx.x;
        float val;
        if (row < 217) {
            int et = row / 31, r = row % 31;
            val = etype_emb[et * 64 + k] + rid_emb[r * 64 + k] + rc_b[k] + rp_b[k];
        } else if (row < 219) {
            val = rc_W[(row - 217) * 64 + k];
        } else {
            val = rp_W[(row - 219) * 64 + k];
        }
        v[k] = val;
    }
    __syncthreads();
    float s = 0.f;
#pragma unroll
    for (int k = 0; k < 64; k++) s += v[k] * Wf[k * 128 + c];
    if (row < 217) table[row * 128 + c] = s + ebias[c];
    else           crcrp[(row - 217) * 128 + c] = s;
}

// ---------------- fused 3-way projection GEMM: [64,64] tile x [64,128] ------
// grid (nblk, 3): blockIdx.y selects (W,C) pair. K=64, TN=128.
__global__ __launch_bounds__(256) void proj3_k(
    const float* __restrict__ A,
    const float* __restrict__ W0, const float* __restrict__ W1, const float* __restrict__ W2,
    float* __restrict__ C0, float* __restrict__ C1, float* __restrict__ C2,
    int nrows)
{
    const float* W = (blockIdx.y == 0) ? W0 : (blockIdx.y == 1) ? W1 : W2;
    float*       C = (blockIdx.y == 0) ? C0 : (blockIdx.y == 1) ? C1 : C2;
    extern __shared__ float sm[];
    float* As = sm;             // [64][64]
    float* Ws = sm + 64 * 64;   // [64][128]
    int tid  = threadIdx.x;
    int row0 = blockIdx.x * 64;
    // load A tile (1024 float4)
#pragma unroll
    for (int i = 0; i < 4; i++) {
        int idx = tid + i * 256;
        int r = idx >> 4, c4 = idx & 15;
        float4 v = make_float4(0.f, 0.f, 0.f, 0.f);
        if (row0 + r < nrows) v = *(const float4*)(A + (size_t)(row0 + r) * 64 + c4 * 4);
        *(float4*)(As + r * 64 + c4 * 4) = v;
    }
    // load W (2048 float4)
#pragma unroll
    for (int i = 0; i < 8; i++) {
        int idx = tid + i * 256;
        *(float4*)(Ws + idx * 4) = *(const float4*)(W + idx * 4);
    }
    __syncthreads();
    int cg = tid & 31, rg = tid >> 5;          // CG=32, RG=8, RPT=8
    float4 acc[8];
#pragma unroll
    for (int i = 0; i < 8; i++) acc[i] = make_float4(0.f, 0.f, 0.f, 0.f);
#pragma unroll 4
    for (int k4 = 0; k4 < 16; k4++) {
        float4 w0 = *(const float4*)(Ws + (k4 * 4 + 0) * 128 + cg * 4);
        float4 w1 = *(const float4*)(Ws + (k4 * 4 + 1) * 128 + cg * 4);
        float4 w2 = *(const float4*)(Ws + (k4 * 4 + 2) * 128 + cg * 4);
        float4 w3 = *(const float4*)(Ws + (k4 * 4 + 3) * 128 + cg * 4);
#pragma unroll
        for (int i = 0; i < 8; i++) {
            float4 a = *(const float4*)(As + (rg * 8 + i) * 64 + k4 * 4);
            acc[i].x = fmaf(a.x, w0.x, acc[i].x); acc[i].y = fmaf(a.x, w0.y, acc[i].y);
            acc[i].z = fmaf(a.x, w0.z, acc[i].z); acc[i].w = fmaf(a.x, w0.w, acc[i].w);
            acc[i].x = fmaf(a.y, w1.x, acc[i].x); acc[i].y = fmaf(a.y, w1.y, acc[i].y);
            acc[i].z = fmaf(a.y, w1.z, acc[i].z); acc[i].w = fmaf(a.y, w1.w, acc[i].w);
            acc[i].x = fmaf(a.z, w2.x, acc[i].x); acc[i].y = fmaf(a.z, w2.y, acc[i].y);
            acc[i].z = fmaf(a.z, w2.z, acc[i].z); acc[i].w = fmaf(a.z, w2.w, acc[i].w);
            acc[i].x = fmaf(a.w, w3.x, acc[i].x); acc[i].y = fmaf(a.w, w3.y, acc[i].y);
            acc[i].z = fmaf(a.w, w3.z, acc[i].z); acc[i].w = fmaf(a.w, w3.w, acc[i].w);
        }
    }
#pragma unroll
    for (int i = 0; i < 8; i++) {
        int r = row0 + rg * 8 + i;
        if (r < nrows) *(float4*)(C + (size_t)r * 128 + cg * 4) = acc[i];
    }
}

// ---------------- fused node MLP: h = relu(hatt@Wm0+bm0)@Wm1+bm1 + h --------
__global__ __launch_bounds__(256) void mlp_fused_k(
    const float* __restrict__ hatt,
    const float* __restrict__ Wm0, const float* __restrict__ bm0,
    const float* __restrict__ Wm1, const float* __restrict__ bm1,
    float* __restrict__ h, float* __restrict__ feats, int foff, int nrows)
{
    extern __shared__ float sm[];
    float* As = sm;              // [64][128]   (later reused as Hs)
    float* Ws = sm + 64 * 128;   // [128][128]  (later first half = Wm1 [128][64])
    int tid  = threadIdx.x;
    int row0 = blockIdx.x * 64;
#pragma unroll
    for (int i = 0; i < 8; i++) {
        int idx = tid + i * 256;
        int r = idx >> 5, c4 = idx & 31;
        float4 v = make_float4(0.f, 0.f, 0.f, 0.f);
        if (row0 + r < nrows) v = *(const float4*)(hatt + (size_t)(row0 + r) * 128 + c4 * 4);
        *(float4*)(As + r * 128 + c4 * 4) = v;
    }
#pragma unroll
    for (int i = 0; i < 16; i++) {
        int idx = tid + i * 256;
        *(float4*)(Ws + idx * 4) = *(const float4*)(Wm0 + idx * 4);
    }
    __syncthreads();
    // GEMM1: K=128, TN=128. CG=32, RG=8, RPT=8.
    {
        int cg = tid & 31, rg = tid >> 5;
        float4 acc[8];
#pragma unroll
        for (int i = 0; i < 8; i++) acc[i] = make_float4(0.f, 0.f, 0.f, 0.f);
#pragma unroll 4
        for (int k4 = 0; k4 < 32; k4++) {
            float4 w0 = *(const float4*)(Ws + (k4 * 4 + 0) * 128 + cg * 4);
            float4 w1 = *(const float4*)(Ws + (k4 * 4 + 1) * 128 + cg * 4);
            float4 w2 = *(const float4*)(Ws + (k4 * 4 + 2) * 128 + cg * 4);
            float4 w3 = *(const float4*)(Ws + (k4 * 4 + 3) * 128 + cg * 4);
#pragma unroll
            for (int i = 0; i < 8; i++) {
                float4 a = *(const float4*)(As + (rg * 8 + i) * 128 + k4 * 4);
                acc[i].x = fmaf(a.x, w0.x, acc[i].x); acc[i].y = fmaf(a.x, w0.y, acc[i].y);
                acc[i].z = fmaf(a.x, w0.z, acc[i].z); acc[i].w = fmaf(a.x, w0.w, acc[i].w);
                acc[i].x = fmaf(a.y, w1.x, acc[i].x); acc[i].y = fmaf(a.y, w1.y, acc[i].y);
                acc[i].z = fmaf(a.y, w1.z, acc[i].z); acc[i].w = fmaf(a.y, w1.w, acc[i].w);
                acc[i].x = fmaf(a.z, w2.x, acc[i].x); acc[i].y = fmaf(a.z, w2.y, acc[i].y);
                acc[i].z = fmaf(a.z, w2.z, acc[i].z); acc[i].w = fmaf(a.z, w2.w, acc[i].w);
                acc[i].x = fmaf(a.w, w3.x, acc[i].x); acc[i].y = fmaf(a.w, w3.y, acc[i].y);
                acc[i].z = fmaf(a.w, w3.z, acc[i].z); acc[i].w = fmaf(a.w, w3.w, acc[i].w);
            }
        }
        float4 bv = *(const float4*)(bm0 + cg * 4);
        __syncthreads();   // all reads of As/Ws done; safe to overwrite
#pragma unroll
        for (int i = 0; i < 8; i++) {
            float4 o;
            o.x = fmaxf(acc[i].x + bv.x, 0.f);
            o.y = fmaxf(acc[i].y + bv.y, 0.f);
            o.z = fmaxf(acc[i].z + bv.z, 0.f);
            o.w = fmaxf(acc[i].w + bv.w, 0.f);
            *(float4*)(As + (rg * 8 + i) * 128 + cg * 4) = o;   // Hs
        }
    }
    // load Wm1 [128][64] into Ws (2048 float4)
#pragma unroll
    for (int i = 0; i < 8; i++) {
        int idx = tid + i * 256;
        *(float4*)(Ws + idx * 4) = *(const float4*)(Wm1 + idx * 4);
    }
    __syncthreads();
    // GEMM2: K=128, TN=64. CG=16, RG=16, RPT=4.
    {
        int cg = tid & 15, rg = tid >> 4;
        float4 acc[4];
#pragma unroll
        for (int i = 0; i < 4; i++) acc[i] = make_float4(0.f, 0.f, 0.f, 0.f);
#pragma unroll 4
        for (int k4 = 0; k4 < 32; k4++) {
            float4 w0 = *(const float4*)(Ws + (k4 * 4 + 0) * 64 + cg * 4);
            float4 w1 = *(const float4*)(Ws + (k4 * 4 + 1) * 64 + cg * 4);
            float4 w2 = *(const float4*)(Ws + (k4 * 4 + 2) * 64 + cg * 4);
            float4 w3 = *(const float4*)(Ws + (k4 * 4 + 3) * 64 + cg * 4);
#pragma unroll
            for (int i = 0; i < 4; i++) {
                float4 a = *(const float4*)(As + (rg * 4 + i) * 128 + k4 * 4);
                acc[i].x = fmaf(a.x, w0.x, acc[i].x); acc[i].y = fmaf(a.x, w0.y, acc[i].y);
                acc[i].z = fmaf(a.x, w0.z, acc[i].z); acc[i].w = fmaf(a.x, w0.w, acc[i].w);
                acc[i].x = fmaf(a.y, w1.x, acc[i].x); acc[i].y = fmaf(a.y, w1.y, acc[i].y);
                acc[i].z = fmaf(a.y, w1.z, acc[i].z); acc[i].w = fmaf(a.y, w1.w, acc[i].w);
                acc[i].x = fmaf(a.z, w2.x, acc[i].x); acc[i].y = fmaf(a.z, w2.y, acc[i].y);
                acc[i].z = fmaf(a.z, w2.z, acc[i].z); acc[i].w = fmaf(a.z, w2.w, acc[i].w);
                acc[i].x = fmaf(a.w, w3.x, acc[i].x); acc[i].y = fmaf(a.w, w3.y, acc[i].y);
                acc[i].z = fmaf(a.w, w3.z, acc[i].z); acc[i].w = fmaf(a.w, w3.w, acc[i].w);
            }
        }
        float4 bv = *(const float4*)(bm1 + cg * 4);
#pragma unroll
        for (int i = 0; i < 4; i++) {
            int r = row0 + rg * 4 + i;
            if (r >= nrows) continue;
            float4 prev = *(const float4*)(h + (size_t)r * 64 + cg * 4);
            float4 o;
            o.x = acc[i].x + bv.x + prev.x;
            o.y = acc[i].y + bv.y + prev.y;
            o.z = acc[i].z + bv.z + prev.z;
            o.w = acc[i].w + bv.w + prev.w;
            *(float4*)(h + (size_t)r * 64 + cg * 4) = o;
            *(float4*)(feats + (size_t)r * FSTR + foff + cg * 4) = o;
        }
    }
}

// ---------------- edge attention logits (warp per edge) ----------------
__global__ __launch_bounds__(256) void edge_attn_k(
    const float* __restrict__ hni, const float* __restrict__ hnj,
    const float* __restrict__ table, const float* __restrict__ crcrp,
    const float* __restrict__ attn,
    const float* __restrict__ att_rc, const float* __restrict__ att_rp,
    const int* __restrict__ src, const int* __restrict__ dst,
    const int* __restrict__ etype, const int* __restrict__ rid,
    float* __restrict__ e_out)
{
    __shared__ float sC[640], sAttn[128];
    for (int i = threadIdx.x; i < 640; i += 256) sC[i] = crcrp[i];
    for (int i = threadIdx.x; i < 128; i += 256) sAttn[i] = attn[i];
    __syncthreads();
    int edge = blockIdx.x * 8 + (threadIdx.x >> 5);
    if (edge >= EE) return;
    int lane = threadIdx.x & 31;
    int s = src[edge], d = dst[edge];
    int tr = etype[edge] * 31 + rid[edge];
    float a0 = att_rc[edge * 2], a1 = att_rc[edge * 2 + 1];
    float p0 = att_rp[edge * 3], p1 = att_rp[edge * 3 + 1], p2 = att_rp[edge * 3 + 2];
    int c4 = lane * 4;
    float4 fi = *(const float4*)(hni + (size_t)s * 128 + c4);
    float4 fj = *(const float4*)(hnj + (size_t)d * 128 + c4);
    float4 ft = *(const float4*)(table + (size_t)tr * 128 + c4);
    float fiv[4] = {fi.x, fi.y, fi.z, fi.w};
    float fjv[4] = {fj.x, fj.y, fj.z, fj.w};
    float ftv[4] = {ft.x, ft.y, ft.z, ft.w};
    float acc = 0.f;
#pragma unroll
    for (int j = 0; j < 4; j++) {
        int c = c4 + j;
        float x = fiv[j] + fjv[j] + ftv[j]
                + a0 * sC[c]       + a1 * sC[128 + c]
                + p0 * sC[256 + c] + p1 * sC[384 + c] + p2 * sC[512 + c];
        x = (x >= 0.f) ? x : 0.2f * x;
        acc += x * sAttn[c];
    }
    acc += __shfl_xor_sync(0xffffffffu, acc, 8);
    acc += __shfl_xor_sync(0xffffffffu, acc, 4);
    acc += __shfl_xor_sync(0xffffffffu, acc, 2);
    acc += __shfl_xor_sync(0xffffffffu, acc, 1);
    if ((lane & 15) == 0) e_out[(size_t)edge * 2 + (lane >> 4)] = acc;
}

// ---------------- segment softmax + aggregation (warp per dst node) ----------
__global__ __launch_bounds__(256) void softmax_agg_k(
    const float* __restrict__ e_log, const int* __restrict__ rowptr,
    const int* __restrict__ eidx, const int* __restrict__ src,
    const float* __restrict__ hnode, float* __restrict__ hatt)
{
    int warp = threadIdx.x >> 5, lane = threadIdx.x & 31;
    int node = blockIdx.x * 8 + warp;
    if (node >= NN) return;
    int i0 = rowptr[node], i1 = rowptr[node + 1];
    float4 acc = make_float4(0.f, 0.f, 0.f, 0.f);
    if (i1 > i0) {
        float m0 = -1e30f, m1 = -1e30f;
        for (int i = i0 + lane; i < i1; i += 32) {
            int idx = eidx[i];
            float2 ev = *(const float2*)(e_log + (size_t)idx * 2);
            m0 = fmaxf(m0, ev.x); m1 = fmaxf(m1, ev.y);
        }
#pragma unroll
        for (int o = 16; o; o >>= 1) {
            m0 = fmaxf(m0, __shfl_xor_sync(0xffffffffu, m0, o));
            m1 = fmaxf(m1, __shfl_xor_sync(0xffffffffu, m1, o));
        }
        float s0 = 0.f, s1 = 0.f;
        for (int i = i0 + lane; i < i1; i += 32) {
            int idx = eidx[i];
            float2 ev = *(const float2*)(e_log + (size_t)idx * 2);
            s0 += __expf(ev.x - m0);
            s1 += __expf(ev.y - m1);
        }
#pragma unroll
        for (int o = 16; o; o >>= 1) {
            s0 += __shfl_xor_sync(0xffffffffu, s0, o);
            s1 += __shfl_xor_sync(0xffffffffu, s1, o);
        }
        int head = lane >> 4;
        float mh   = head ? m1 : m0;
        float invh = 1.f / ((head ? s1 : s0) + 1e-9f);
        int c4 = lane * 4;
        for (int i = i0; i < i1; i++) {
            int idx = eidx[i];
            int sn  = src[idx];
            float alpha = __expf(e_log[(size_t)idx * 2 + head] - mh) * invh;
            float4 v = *(const float4*)(hnode + (size_t)sn * 128 + c4);
            acc.x += alpha * v.x; acc.y += alpha * v.y;
            acc.z += alpha * v.z; acc.w += alpha * v.w;
        }
    }
    *(float4*)(hatt + (size_t)node * 128 + lane * 4) = acc;
}

// ---------------- graph max pooling + output assembly ----------------
__global__ void pool_max_k(const float* __restrict__ feats, float* __restrict__ gmax) {
    int b = blockIdx.x;
    int f = blockIdx.y * 64 + (threadIdx.x & 63);
    int grp = threadIdx.x >> 6;
    float m = -1e30f;
    if (f < 266) {
        const float* base = feats + (size_t)b * NPG * FSTR;
        for (int n = grp; n < NPG; n += 4)
            m = fmaxf(m, base[(size_t)n * FSTR + f]);
    }
    __shared__ float sm[256];
    sm[threadIdx.x] = m;
    __syncthreads();
    if (grp == 0 && f < 266) {
        m = fmaxf(fmaxf(sm[threadIdx.x], sm[threadIdx.x + 64]),
                  fmaxf(sm[threadIdx.x + 128], sm[threadIdx.x + 192]));
        gmax[b * FSTR + f] = m;
    }
}

__global__ void write_out_k(const float* __restrict__ feats,
                            const float* __restrict__ gmax,
                            float* __restrict__ out) {
    long long idx = (long long)blockIdx.x * 256 + threadIdx.x;
    const long long total = (long long)NB * NPG * 532;
    if (idx >= total) return;
    int c = (int)(idx % 532);
    long long bn = idx / 532;
    int b = (int)(bn / NPG);
    int cl = (c < 266) ? c : (c - 266);
    int ci = (cl < 10) ? (256 + cl) : (cl - 10);
    out[idx] = (c < 266) ? feats[bn * FSTR + ci] : gmax[b * FSTR + ci];
}

// ---------------- host launcher ----------------
extern "C" void kernel_launch(void* const* d_in, const int* in_sizes, int n_in,
                              void* d_out, int out_size)
{
    const float* feat      = (const float*)d_in[0];
    const float* att_rc    = (const float*)d_in[1];
    const float* att_rp    = (const float*)d_in[2];
    const float* etype_emb = (const float*)d_in[3];
    const float* rid_emb   = (const float*)d_in[4];
    const float* rc_W      = (const float*)d_in[5];
    const float* rc_b      = (const float*)d_in[6];
    const float* rp_W      = (const float*)d_in[7];
    const float* rp_b      = (const float*)d_in[8];
    const float* fe_W0     = (const float*)d_in[9];
    const float* fe_b0     = (const float*)d_in[10];
    const float* fe_W1     = (const float*)d_in[11];
    const float* fe_b1     = (const float*)d_in[12];
    const float* W_ni      = (const float*)d_in[13];
    const float* W_nj      = (const float*)d_in[14];
    const float* W_fij     = (const float*)d_in[15];
    const float* W_node    = (const float*)d_in[16];
    const float* attn      = (const float*)d_in[17];
    const float* egat_bias = (const float*)d_in[18];
    const float* Wm0       = (const float*)d_in[19];
    const float* bm0       = (const float*)d_in[20];
    const float* Wm1       = (const float*)d_in[21];
    const float* bm1       = (const float*)d_in[22];
    const int*   src       = (const int*)d_in[23];
    const int*   dst       = (const int*)d_in[24];
    const int*   etype     = (const int*)d_in[25];
    const int*   rid       = (const int*)d_in[26];
    float* out = (float*)d_out;

    float *p_h, *p_hni, *p_hnj, *p_hnode, *p_hatt, *p_feats, *p_e;
    float *p_table, *p_crcrp, *p_gmax;
    int *p_deg, *p_rowptr, *p_cursor, *p_eidx, *p_bsum;
    cudaGetSymbolAddress((void**)&p_h,      g_h);
    cudaGetSymbolAddress((void**)&p_hni,    g_hni);
    cudaGetSymbolAddress((void**)&p_hnj,    g_hnj);
    cudaGetSymbolAddress((void**)&p_hnode,  g_hnode);
    cudaGetSymbolAddress((void**)&p_hatt,   g_hatt);
    cudaGetSymbolAddress((void**)&p_feats,  g_feats);
    cudaGetSymbolAddress((void**)&p_e,      g_e);
    cudaGetSymbolAddress((void**)&p_table,  g_table);
    cudaGetSymbolAddress((void**)&p_crcrp,  g_crcrp);
    cudaGetSymbolAddress((void**)&p_gmax,   g_gmax);
    cudaGetSymbolAddress((void**)&p_deg,    g_deg);
    cudaGetSymbolAddress((void**)&p_rowptr, g_rowptr);
    cudaGetSymbolAddress((void**)&p_cursor, g_cursor);
    cudaGetSymbolAddress((void**)&p_eidx,   g_eidx);
    cudaGetSymbolAddress((void**)&p_bsum,   g_bsum);

    const int SH_PROJ = (64 * 64 + 64 * 128) * 4;     // 48 KB
    const int SH_MLP  = (64 * 128 + 128 * 128) * 4;   // 96 KB
    cudaFuncSetAttribute((const void*)proj3_k,
                         cudaFuncAttributeMaxDynamicSharedMemorySize, SH_PROJ);
    cudaFuncSetAttribute((const void*)mlp_fused_k,
                         cudaFuncAttributeMaxDynamicSharedMemorySize, SH_MLP);

    const int GRID_N = (NN + 63) / 64;      // 782
    const int GRID_E = (EE + 255) / 256;    // 1954
    const int NBLK_SCAN = (NN + 255) / 256; // 196

    // 1) feature encoder
    fe_mlp_k<<<(NN + 255) / 256, 256>>>(feat, fe_W0, fe_b0, fe_W1, fe_b1, p_h, p_feats);

    // 2) CSR by dst (parallel scan)
    zero_int_k<<<NBLK_SCAN, 256>>>(p_deg, NN);
    hist_k<<<GRID_E, 256>>>(dst, p_deg);
    scan_partial_k<<<NBLK_SCAN, 256>>>(p_deg, p_bsum);
    scan_bsum_k<<<1, 256>>>(p_bsum, NBLK_SCAN);
    scan_final_k<<<NBLK_SCAN, 256>>>(p_deg, p_bsum, p_rowptr, p_cursor);
    scatter_k<<<GRID_E, 256>>>(dst, p_cursor, p_eidx);

    // 3) EGAT layers
    for (int l = 0; l < 3; l++) {
        precompute_fij_k<<<222, 128>>>(etype_emb, rid_emb, rc_W, rp_W, rc_b, rp_b,
                                       W_fij + l * 64 * 128, egat_bias + l * 128,
                                       p_table, p_crcrp);
        proj3_k<<<dim3(GRID_N, 3), 256, SH_PROJ>>>(
            p_h, W_ni + l * 64 * 128, W_nj + l * 64 * 128, W_node + l * 64 * 128,
            p_hni, p_hnj, p_hnode, NN);

        edge_attn_k<<<EE / 8, 256>>>(p_hni, p_hnj, p_table, p_crcrp,
                                     attn + l * 128, att_rc, att_rp,
                                     src, dst, etype, rid, p_e);

        softmax_agg_k<<<NN / 8, 256>>>(p_e, p_rowptr, p_eidx, src, p_hnode, p_hatt);

        mlp_fused_k<<<GRID_N, 256, SH_MLP>>>(
            p_hatt, Wm0 + l * 128 * 128, bm0 + l * 128,
            Wm1 + l * 128 * 64, bm1 + l * 64,
            p_h, p_feats, 64 * (l + 1), NN);
    }

    // 4) pooling + output
    pool_max_k<<<dim3(NB, 5), 256>>>(p_feats, p_gmax);
    long long total = (long long)NB * NPG * 532;
    write_out_k<<<(int)((total + 255) / 256), 256>>>(p_feats, p_gmax, out);
}

// round 13
// speedup vs baseline: 1.1729x; 1.1729x over previous
#include <cuda_runtime.h>
#include <cuda_bf16.h>
#include <cstdint>
#include <cstddef>

// ---------------- problem constants ----------------
#define NN     50000
#define EE     500000
#define NPG    6250
#define NB     8
#define FSTR   272
#define NSPLIT 13
#define PS     481   // nodes per pooling split (13*481 >= 6250)
// internal feats layout per node: [h0(64) h1(64) h2(64) h3(64) feat(10) pad(6)]

// ---------------- device scratch ----------------
__device__ __align__(16) float g_h     [NN * 64];
__device__ __align__(16) float g_hni   [NN * 128];
__device__ __align__(16) float g_hnj   [NN * 128];
__device__ __align__(16) float g_hnode [NN * 128];
__device__ __align__(16) float g_hatt  [NN * 128];
__device__ __align__(16) float g_feats [NN * FSTR];
__device__ __align__(16) float g_e     [EE * 2];
__device__ int   g_deg   [NN];
__device__ int   g_rowptr[NN + 1];
__device__ int   g_cursor[NN];
__device__ int   g_eidx  [EE];
__device__ int   g_bsum  [256];
__device__ __align__(16) float g_table [217 * 128];
__device__ __align__(16) float g_crcrp [5 * 128];
__device__ __align__(16) float g_gmax  [NB * FSTR];
__device__ __align__(16) float g_pool  [NB * 5 * NSPLIT * 64];

// ---------------- feature-encoder MLP (feat -> h0) ----------------
__global__ __launch_bounds__(256) void fe_mlp_k(
    const float* __restrict__ feat, const float* __restrict__ W0,
    const float* __restrict__ b0,   const float* __restrict__ W1,
    const float* __restrict__ b1,   float* __restrict__ h,
    float* __restrict__ feats)
{
    __shared__ float sW0[640], sb0[64], sW1[4096], sb1[64];
    int tid = threadIdx.x;
    for (int i = tid; i < 640;  i += 256) sW0[i] = W0[i];
    for (int i = tid; i < 4096; i += 256) sW1[i] = W1[i];
    if (tid < 64) { sb0[tid] = b0[tid]; sb1[tid] = b1[tid]; }
    __syncthreads();
    int n = blockIdx.x * 256 + tid;
    if (n >= NN) return;
    float f[10];
#pragma unroll
    for (int i = 0; i < 10; i++) {
        f[i] = feat[n * 10 + i];
        feats[(size_t)n * FSTR + 256 + i] = f[i];
    }
    float hid[64];
#pragma unroll
    for (int c = 0; c < 64; c++) {
        float s = sb0[c];
#pragma unroll
        for (int k = 0; k < 10; k++) s += f[k] * sW0[k * 64 + c];
        hid[c] = fmaxf(s, 0.f);
    }
    for (int c = 0; c < 64; c++) {
        float s = sb1[c];
#pragma unroll
        for (int k = 0; k < 64; k++) s += hid[k] * sW1[k * 64 + c];
        h[(size_t)n * 64 + c] = s;
        feats[(size_t)n * FSTR + c] = s;
    }
}

// ---------------- CSR build ----------------
__global__ void zero_int_k(int* p, int n) {
    int i = blockIdx.x * 256 + threadIdx.x;
    if (i < n) p[i] = 0;
}
__global__ void hist_k(const int* __restrict__ dst, int* deg) {
    int e = blockIdx.x * 256 + threadIdx.x;
    if (e < EE) atomicAdd(&deg[dst[e]], 1);
}
__global__ void scan_partial_k(const int* __restrict__ deg, int* bsum) {
    __shared__ int s[256];
    int i = blockIdx.x * 256 + threadIdx.x;
    s[threadIdx.x] = (i < NN) ? deg[i] : 0;
    __syncthreads();
#pragma unroll
    for (int o = 128; o; o >>= 1) {
        if (threadIdx.x < o) s[threadIdx.x] += s[threadIdx.x + o];
        __syncthreads();
    }
    if (threadIdx.x == 0) bsum[blockIdx.x] = s[0];
}
__global__ void scan_bsum_k(int* bsum, int nb) {
    __shared__ int s[256];
    int t = threadIdx.x;
    int v = (t < nb) ? bsum[t] : 0;
    s[t] = v;
    __syncthreads();
#pragma unroll
    for (int o = 1; o < 256; o <<= 1) {
        int x = (t >= o) ? s[t - o] : 0;
        __syncthreads();
        s[t] += x;
        __syncthreads();
    }
    if (t < nb) bsum[t] = s[t] - v;   // exclusive
}
__global__ void scan_final_k(const int* __restrict__ deg, const int* __restrict__ bsum,
                             int* rowptr, int* cursor) {
    __shared__ int s[256];
    int i = blockIdx.x * 256 + threadIdx.x;
    int v = (i < NN) ? deg[i] : 0;
    s[threadIdx.x] = v;
    __syncthreads();
#pragma unroll
    for (int o = 1; o < 256; o <<= 1) {
        int x = (threadIdx.x >= o) ? s[threadIdx.x - o] : 0;
        __syncthreads();
        s[threadIdx.x] += x;
        __syncthreads();
    }
    if (i < NN) {
        int off = bsum[blockIdx.x] + s[threadIdx.x] - v;
        rowptr[i] = off;
        cursor[i] = off;
    }
    if (i == NN - 1) rowptr[NN] = EE;
}
__global__ void scatter_k(const int* __restrict__ dst, int* cursor, int* eidx) {
    int e = blockIdx.x * 256 + threadIdx.x;
    if (e < EE) {
        int pos = atomicAdd(&cursor[dst[e]], 1);
        eidx[pos] = e;
    }
}

// ---------------- per-layer f_fij precompute ----------------
__global__ void precompute_fij_k(
    const float* __restrict__ etype_emb, const float* __restrict__ rid_emb,
    const float* __restrict__ rc_W, const float* __restrict__ rp_W,
    const float* __restrict__ rc_b, const float* __restrict__ rp_b,
    const float* __restrict__ Wf,   const float* __restrict__ ebias,
    float* __restrict__ table, float* __restrict__ crcrp)
{
    int row = blockIdx.x;         // 0..221
    int c   = threadIdx.x;        // 0..127
    __shared__ float v[64];
    if (threadIdx.x < 64) {
        int k = threadIdx.x;
        float val;
        if (row < 217) {
            int et = row / 31, r = row % 31;
            val = etype_emb[et * 64 + k] + rid_emb[r * 64 + k] + rc_b[k] + rp_b[k];
        } else if (row < 219) {
            val = rc_W[(row - 217) * 64 + k];
        } else {
            val = rp_W[(row - 219) * 64 + k];
        }
        v[k] = val;
    }
    __syncthreads();
    float s = 0.f;
#pragma unroll
    for (int k = 0; k < 64; k++) s += v[k] * Wf[k * 128 + c];
    if (row < 217) table[row * 128 + c] = s + ebias[c];
    else           crcrp[(row - 217) * 128 + c] = s;
}

// ---------------- fused 3-way projection GEMM: [64,64] tile x [64,128] ------
__global__ __launch_bounds__(256) void proj3_k(
    const float* __restrict__ A,
    const float* __restrict__ W0, const float* __restrict__ W1, const float* __restrict__ W2,
    float* __restrict__ C0, float* __restrict__ C1, float* __restrict__ C2,
    int nrows)
{
    const float* W = (blockIdx.y == 0) ? W0 : (blockIdx.y == 1) ? W1 : W2;
    float*       C = (blockIdx.y == 0) ? C0 : (blockIdx.y == 1) ? C1 : C2;
    extern __shared__ float sm[];
    float* As = sm;             // [64][64]
    float* Ws = sm + 64 * 64;   // [64][128]
    int tid  = threadIdx.x;
    int row0 = blockIdx.x * 64;
#pragma unroll
    for (int i = 0; i < 4; i++) {
        int idx = tid + i * 256;
        int r = idx >> 4, c4 = idx & 15;
        float4 v = make_float4(0.f, 0.f, 0.f, 0.f);
        if (row0 + r < nrows) v = *(const float4*)(A + (size_t)(row0 + r) * 64 + c4 * 4);
        *(float4*)(As + r * 64 + c4 * 4) = v;
    }
#pragma unroll
    for (int i = 0; i < 8; i++) {
        int idx = tid + i * 256;
        *(float4*)(Ws + idx * 4) = *(const float4*)(W + idx * 4);
    }
    __syncthreads();
    int cg = tid & 31, rg = tid >> 5;          // CG=32, RG=8, RPT=8
    float4 acc[8];
#pragma unroll
    for (int i = 0; i < 8; i++) acc[i] = make_float4(0.f, 0.f, 0.f, 0.f);
#pragma unroll 4
    for (int k4 = 0; k4 < 16; k4++) {
        float4 w0 = *(const float4*)(Ws + (k4 * 4 + 0) * 128 + cg * 4);
        float4 w1 = *(const float4*)(Ws + (k4 * 4 + 1) * 128 + cg * 4);
        float4 w2 = *(const float4*)(Ws + (k4 * 4 + 2) * 128 + cg * 4);
        float4 w3 = *(const float4*)(Ws + (k4 * 4 + 3) * 128 + cg * 4);
#pragma unroll
        for (int i = 0; i < 8; i++) {
            float4 a = *(const float4*)(As + (rg * 8 + i) * 64 + k4 * 4);
            acc[i].x = fmaf(a.x, w0.x, acc[i].x); acc[i].y = fmaf(a.x, w0.y, acc[i].y);
            acc[i].z = fmaf(a.x, w0.z, acc[i].z); acc[i].w = fmaf(a.x, w0.w, acc[i].w);
            acc[i].x = fmaf(a.y, w1.x, acc[i].x); acc[i].y = fmaf(a.y, w1.y, acc[i].y);
            acc[i].z = fmaf(a.y, w1.z, acc[i].z); acc[i].w = fmaf(a.y, w1.w, acc[i].w);
            acc[i].x = fmaf(a.z, w2.x, acc[i].x); acc[i].y = fmaf(a.z, w2.y, acc[i].y);
            acc[i].z = fmaf(a.z, w2.z, acc[i].z); acc[i].w = fmaf(a.z, w2.w, acc[i].w);
            acc[i].x = fmaf(a.w, w3.x, acc[i].x); acc[i].y = fmaf(a.w, w3.y, acc[i].y);
            acc[i].z = fmaf(a.w, w3.z, acc[i].z); acc[i].w = fmaf(a.w, w3.w, acc[i].w);
        }
    }
#pragma unroll
    for (int i = 0; i < 8; i++) {
        int r = row0 + rg * 8 + i;
        if (r < nrows) *(float4*)(C + (size_t)r * 128 + cg * 4) = acc[i];
    }
}

// ---------------- fused node MLP: h = relu(hatt@Wm0+bm0)@Wm1+bm1 + h --------
__global__ __launch_bounds__(256) void mlp_fused_k(
    const float* __restrict__ hatt,
    const float* __restrict__ Wm0, const float* __restrict__ bm0,
    const float* __restrict__ Wm1, const float* __restrict__ bm1,
    float* __restrict__ h, float* __restrict__ feats, int foff, int nrows)
{
    extern __shared__ float sm[];
    float* As = sm;              // [64][128]   (later reused as Hs)
    float* Ws = sm + 64 * 128;   // [128][128]
    int tid  = threadIdx.x;
    int row0 = blockIdx.x * 64;
#pragma unroll
    for (int i = 0; i < 8; i++) {
        int idx = tid + i * 256;
        int r = idx >> 5, c4 = idx & 31;
        float4 v = make_float4(0.f, 0.f, 0.f, 0.f);
        if (row0 + r < nrows) v = *(const float4*)(hatt + (size_t)(row0 + r) * 128 + c4 * 4);
        *(float4*)(As + r * 128 + c4 * 4) = v;
    }
#pragma unroll
    for (int i = 0; i < 16; i++) {
        int idx = tid + i * 256;
        *(float4*)(Ws + idx * 4) = *(const float4*)(Wm0 + idx * 4);
    }
    __syncthreads();
    {
        int cg = tid & 31, rg = tid >> 5;
        float4 acc[8];
#pragma unroll
        for (int i = 0; i < 8; i++) acc[i] = make_float4(0.f, 0.f, 0.f, 0.f);
#pragma unroll 4
        for (int k4 = 0; k4 < 32; k4++) {
            float4 w0 = *(const float4*)(Ws + (k4 * 4 + 0) * 128 + cg * 4);
            float4 w1 = *(const float4*)(Ws + (k4 * 4 + 1) * 128 + cg * 4);
            float4 w2 = *(const float4*)(Ws + (k4 * 4 + 2) * 128 + cg * 4);
            float4 w3 = *(const float4*)(Ws + (k4 * 4 + 3) * 128 + cg * 4);
#pragma unroll
            for (int i = 0; i < 8; i++) {
                float4 a = *(const float4*)(As + (rg * 8 + i) * 128 + k4 * 4);
                acc[i].x = fmaf(a.x, w0.x, acc[i].x); acc[i].y = fmaf(a.x, w0.y, acc[i].y);
                acc[i].z = fmaf(a.x, w0.z, acc[i].z); acc[i].w = fmaf(a.x, w0.w, acc[i].w);
                acc[i].x = fmaf(a.y, w1.x, acc[i].x); acc[i].y = fmaf(a.y, w1.y, acc[i].y);
                acc[i].z = fmaf(a.y, w1.z, acc[i].z); acc[i].w = fmaf(a.y, w1.w, acc[i].w);
                acc[i].x = fmaf(a.z, w2.x, acc[i].x); acc[i].y = fmaf(a.z, w2.y, acc[i].y);
                acc[i].z = fmaf(a.z, w2.z, acc[i].z); acc[i].w = fmaf(a.z, w2.w, acc[i].w);
                acc[i].x = fmaf(a.w, w3.x, acc[i].x); acc[i].y = fmaf(a.w, w3.y, acc[i].y);
                acc[i].z = fmaf(a.w, w3.z, acc[i].z); acc[i].w = fmaf(a.w, w3.w, acc[i].w);
            }
        }
        float4 bv = *(const float4*)(bm0 + cg * 4);
        __syncthreads();
#pragma unroll
        for (int i = 0; i < 8; i++) {
            float4 o;
            o.x = fmaxf(acc[i].x + bv.x, 0.f);
            o.y = fmaxf(acc[i].y + bv.y, 0.f);
            o.z = fmaxf(acc[i].z + bv.z, 0.f);
            o.w = fmaxf(acc[i].w + bv.w, 0.f);
            *(float4*)(As + (rg * 8 + i) * 128 + cg * 4) = o;
        }
    }
#pragma unroll
    for (int i = 0; i < 8; i++) {
        int idx = tid + i * 256;
        *(float4*)(Ws + idx * 4) = *(const float4*)(Wm1 + idx * 4);
    }
    __syncthreads();
    {
        int cg = tid & 15, rg = tid >> 4;
        float4 acc[4];
#pragma unroll
        for (int i = 0; i < 4; i++) acc[i] = make_float4(0.f, 0.f, 0.f, 0.f);
#pragma unroll 4
        for (int k4 = 0; k4 < 32; k4++) {
            float4 w0 = *(const float4*)(Ws + (k4 * 4 + 0) * 64 + cg * 4);
            float4 w1 = *(const float4*)(Ws + (k4 * 4 + 1) * 64 + cg * 4);
            float4 w2 = *(const float4*)(Ws + (k4 * 4 + 2) * 64 + cg * 4);
            float4 w3 = *(const float4*)(Ws + (k4 * 4 + 3) * 64 + cg * 4);
#pragma unroll
            for (int i = 0; i < 4; i++) {
                float4 a = *(const float4*)(As + (rg * 4 + i) * 128 + k4 * 4);
                acc[i].x = fmaf(a.x, w0.x, acc[i].x); acc[i].y = fmaf(a.x, w0.y, acc[i].y);
                acc[i].z = fmaf(a.x, w0.z, acc[i].z); acc[i].w = fmaf(a.x, w0.w, acc[i].w);
                acc[i].x = fmaf(a.y, w1.x, acc[i].x); acc[i].y = fmaf(a.y, w1.y, acc[i].y);
                acc[i].z = fmaf(a.y, w1.z, acc[i].z); acc[i].w = fmaf(a.y, w1.w, acc[i].w);
                acc[i].x = fmaf(a.z, w2.x, acc[i].x); acc[i].y = fmaf(a.z, w2.y, acc[i].y);
                acc[i].z = fmaf(a.z, w2.z, acc[i].z); acc[i].w = fmaf(a.z, w2.w, acc[i].w);
                acc[i].x = fmaf(a.w, w3.x, acc[i].x); acc[i].y = fmaf(a.w, w3.y, acc[i].y);
                acc[i].z = fmaf(a.w, w3.z, acc[i].z); acc[i].w = fmaf(a.w, w3.w, acc[i].w);
            }
        }
        float4 bv = *(const float4*)(bm1 + cg * 4);
#pragma unroll
        for (int i = 0; i < 4; i++) {
            int r = row0 + rg * 4 + i;
            if (r >= nrows) continue;
            float4 prev = *(const float4*)(h + (size_t)r * 64 + cg * 4);
            float4 o;
            o.x = acc[i].x + bv.x + prev.x;
            o.y = acc[i].y + bv.y + prev.y;
            o.z = acc[i].z + bv.z + prev.z;
            o.w = acc[i].w + bv.w + prev.w;
            *(float4*)(h + (size_t)r * 64 + cg * 4) = o;
            *(float4*)(feats + (size_t)r * FSTR + foff + cg * 4) = o;
        }
    }
}

// ---------------- edge attention logits (warp per edge) ----------------
__global__ __launch_bounds__(256) void edge_attn_k(
    const float* __restrict__ hni, const float* __restrict__ hnj,
    const float* __restrict__ table, const float* __restrict__ crcrp,
    const float* __restrict__ attn,
    const float* __restrict__ att_rc, const float* __restrict__ att_rp,
    const int* __restrict__ src, const int* __restrict__ dst,
    const int* __restrict__ etype, const int* __restrict__ rid,
    float* __restrict__ e_out)
{
    __shared__ float sC[640], sAttn[128];
    for (int i = threadIdx.x; i < 640; i += 256) sC[i] = crcrp[i];
    for (int i = threadIdx.x; i < 128; i += 256) sAttn[i] = attn[i];
    __syncthreads();
    int edge = blockIdx.x * 8 + (threadIdx.x >> 5);
    if (edge >= EE) return;
    int lane = threadIdx.x & 31;
    int s = src[edge], d = dst[edge];
    int tr = etype[edge] * 31 + rid[edge];
    float a0 = att_rc[edge * 2], a1 = att_rc[edge * 2 + 1];
    float p0 = att_rp[edge * 3], p1 = att_rp[edge * 3 + 1], p2 = att_rp[edge * 3 + 2];
    int c4 = lane * 4;
    float4 fi = *(const float4*)(hni + (size_t)s * 128 + c4);
    float4 fj = *(const float4*)(hnj + (size_t)d * 128 + c4);
    float4 ft = *(const float4*)(table + (size_t)tr * 128 + c4);
    float fiv[4] = {fi.x, fi.y, fi.z, fi.w};
    float fjv[4] = {fj.x, fj.y, fj.z, fj.w};
    float ftv[4] = {ft.x, ft.y, ft.z, ft.w};
    float acc = 0.f;
#pragma unroll
    for (int j = 0; j < 4; j++) {
        int c = c4 + j;
        float x = fiv[j] + fjv[j] + ftv[j]
                + a0 * sC[c]       + a1 * sC[128 + c]
                + p0 * sC[256 + c] + p1 * sC[384 + c] + p2 * sC[512 + c];
        x = (x >= 0.f) ? x : 0.2f * x;
        acc += x * sAttn[c];
    }
    acc += __shfl_xor_sync(0xffffffffu, acc, 8);
    acc += __shfl_xor_sync(0xffffffffu, acc, 4);
    acc += __shfl_xor_sync(0xffffffffu, acc, 2);
    acc += __shfl_xor_sync(0xffffffffu, acc, 1);
    if ((lane & 15) == 0) e_out[(size_t)edge * 2 + (lane >> 4)] = acc;
}

// ---------------- segment softmax + aggregation (warp per dst node) ----------
// online max+sum (single pass over e_log), prefetched aggregation loop
__global__ __launch_bounds__(256) void softmax_agg_k(
    const float* __restrict__ e_log, const int* __restrict__ rowptr,
    const int* __restrict__ eidx, const int* __restrict__ src,
    const float* __restrict__ hnode, float* __restrict__ hatt)
{
    int warp = threadIdx.x >> 5, lane = threadIdx.x & 31;
    int node = blockIdx.x * 8 + warp;
    if (node >= NN) return;
    int i0 = rowptr[node], i1 = rowptr[node + 1];
    float4 acc = make_float4(0.f, 0.f, 0.f, 0.f);
    if (i1 > i0) {
        // online max+sum per lane
        float m0 = -1e30f, m1 = -1e30f, s0 = 0.f, s1 = 0.f;
        for (int i = i0 + lane; i < i1; i += 32) {
            int idx = eidx[i];
            float2 ev = *(const float2*)(e_log + (size_t)idx * 2);
            float n0 = fmaxf(m0, ev.x);
            s0 = s0 * __expf(m0 - n0) + __expf(ev.x - n0);
            m0 = n0;
            float n1 = fmaxf(m1, ev.y);
            s1 = s1 * __expf(m1 - n1) + __expf(ev.y - n1);
            m1 = n1;
        }
        // warp merge
#pragma unroll
        for (int o = 16; o; o >>= 1) {
            float mo0 = __shfl_xor_sync(0xffffffffu, m0, o);
            float so0 = __shfl_xor_sync(0xffffffffu, s0, o);
            float mn0 = fmaxf(m0, mo0);
            s0 = s0 * __expf(m0 - mn0) + so0 * __expf(mo0 - mn0);
            m0 = mn0;
            float mo1 = __shfl_xor_sync(0xffffffffu, m1, o);
            float so1 = __shfl_xor_sync(0xffffffffu, s1, o);
            float mn1 = fmaxf(m1, mo1);
            s1 = s1 * __expf(m1 - mn1) + so1 * __expf(mo1 - mn1);
            m1 = mn1;
        }
        int head = lane >> 4;
        float mh   = head ? m1 : m0;
        float invh = 1.f / ((head ? s1 : s0) + 1e-9f);
        int c4 = lane * 4;
        int idx = eidx[i0];
        for (int i = i0; i < i1; i++) {
            int idx_n = (i + 1 < i1) ? eidx[i + 1] : 0;
            int sn = src[idx];
            float el = e_log[(size_t)idx * 2 + head];
            float4 v = *(const float4*)(hnode + (size_t)sn * 128 + c4);
            float alpha = __expf(el - mh) * invh;
            acc.x += alpha * v.x; acc.y += alpha * v.y;
            acc.z += alpha * v.z; acc.w += alpha * v.w;
            idx = idx_n;
        }
    }
    *(float4*)(hatt + (size_t)node * 128 + lane * 4) = acc;
}

// ---------------- graph max pooling (2-stage) + output assembly --------------
__global__ void pool_part_k(const float* __restrict__ feats, float* __restrict__ part) {
    int b = blockIdx.x, fc = blockIdx.y, sp = blockIdx.z;
    int fl = threadIdx.x & 63;
    int f  = fc * 64 + fl;
    int grp = threadIdx.x >> 6;
    int n0 = sp * PS, n1 = n0 + PS;
    if (n1 > NPG) n1 = NPG;
    float m = -1e30f;
    if (f < 266) {
        const float* base = feats + (size_t)b * NPG * FSTR;
        for (int n = n0 + grp; n < n1; n += 4)
            m = fmaxf(m, base[(size_t)n * FSTR + f]);
    }
    __shared__ float sm[256];
    sm[threadIdx.x] = m;
    __syncthreads();
    if (grp == 0) {
        m = fmaxf(fmaxf(sm[threadIdx.x], sm[threadIdx.x + 64]),
                  fmaxf(sm[threadIdx.x + 128], sm[threadIdx.x + 192]));
        part[((b * 5 + fc) * NSPLIT + sp) * 64 + fl] = m;
    }
}
__global__ void pool_reduce_k(const float* __restrict__ part, float* __restrict__ gmax) {
    int b = blockIdx.x, fc = blockIdx.y, t = threadIdx.x;   // block 64
    float m = -1e30f;
#pragma unroll
    for (int sp = 0; sp < NSPLIT; sp++)
        m = fmaxf(m, part[((b * 5 + fc) * NSPLIT + sp) * 64 + t]);
    int f = fc * 64 + t;
    if (f < 266) gmax[b * FSTR + f] = m;
}

__global__ void write_out_k(const float* __restrict__ feats,
                            const float* __restrict__ gmax,
                            float* __restrict__ out) {
    long long idx = (long long)blockIdx.x * 256 + threadIdx.x;
    const long long total = (long long)NB * NPG * 532;
    if (idx >= total) return;
    int c = (int)(idx % 532);
    long long bn = idx / 532;
    int b = (int)(bn / NPG);
    int cl = (c < 266) ? c : (c - 266);
    int ci = (cl < 10) ? (256 + cl) : (cl - 10);
    out[idx] = (c < 266) ? feats[bn * FSTR + ci] : gmax[b * FSTR + ci];
}

// ---------------- host launcher ----------------
extern "C" void kernel_launch(void* const* d_in, const int* in_sizes, int n_in,
                              void* d_out, int out_size)
{
    const float* feat      = (const float*)d_in[0];
    const float* att_rc    = (const float*)d_in[1];
    const float* att_rp    = (const float*)d_in[2];
    const float* etype_emb = (const float*)d_in[3];
    const float* rid_emb   = (const float*)d_in[4];
    const float* rc_W      = (const float*)d_in[5];
    const float* rc_b      = (const float*)d_in[6];
    const float* rp_W      = (const float*)d_in[7];
    const float* rp_b      = (const float*)d_in[8];
    const float* fe_W0     = (const float*)d_in[9];
    const float* fe_b0     = (const float*)d_in[10];
    const float* fe_W1     = (const float*)d_in[11];
    const float* fe_b1     = (const float*)d_in[12];
    const float* W_ni      = (const float*)d_in[13];
    const float* W_nj      = (const float*)d_in[14];
    const float* W_fij     = (const float*)d_in[15];
    const float* W_node    = (const float*)d_in[16];
    const float* attn      = (const float*)d_in[17];
    const float* egat_bias = (const float*)d_in[18];
    const float* Wm0       = (const float*)d_in[19];
    const float* bm0       = (const float*)d_in[20];
    const float* Wm1       = (const float*)d_in[21];
    const float* bm1       = (const float*)d_in[22];
    const int*   src       = (const int*)d_in[23];
    const int*   dst       = (const int*)d_in[24];
    const int*   etype     = (const int*)d_in[25];
    const int*   rid       = (const int*)d_in[26];
    float* out = (float*)d_out;

    float *p_h, *p_hni, *p_hnj, *p_hnode, *p_hatt, *p_feats, *p_e;
    float *p_table, *p_crcrp, *p_gmax, *p_pool;
    int *p_deg, *p_rowptr, *p_cursor, *p_eidx, *p_bsum;
    cudaGetSymbolAddress((void**)&p_h,      g_h);
    cudaGetSymbolAddress((void**)&p_hni,    g_hni);
    cudaGetSymbolAddress((void**)&p_hnj,    g_hnj);
    cudaGetSymbolAddress((void**)&p_hnode,  g_hnode);
    cudaGetSymbolAddress((void**)&p_hatt,   g_hatt);
    cudaGetSymbolAddress((void**)&p_feats,  g_feats);
    cudaGetSymbolAddress((void**)&p_e,      g_e);
    cudaGetSymbolAddress((void**)&p_table,  g_table);
    cudaGetSymbolAddress((void**)&p_crcrp,  g_crcrp);
    cudaGetSymbolAddress((void**)&p_gmax,   g_gmax);
    cudaGetSymbolAddress((void**)&p_pool,   g_pool);
    cudaGetSymbolAddress((void**)&p_deg,    g_deg);
    cudaGetSymbolAddress((void**)&p_rowptr, g_rowptr);
    cudaGetSymbolAddress((void**)&p_cursor, g_cursor);
    cudaGetSymbolAddress((void**)&p_eidx,   g_eidx);
    cudaGetSymbolAddress((void**)&p_bsum,   g_bsum);

    const int SH_PROJ = (64 * 64 + 64 * 128) * 4;     // 48 KB
    const int SH_MLP  = (64 * 128 + 128 * 128) * 4;   // 96 KB
    cudaFuncSetAttribute((const void*)proj3_k,
                         cudaFuncAttributeMaxDynamicSharedMemorySize, SH_PROJ);
    cudaFuncSetAttribute((const void*)mlp_fused_k,
                         cudaFuncAttributeMaxDynamicSharedMemorySize, SH_MLP);

    const int GRID_N = (NN + 63) / 64;      // 782
    const int GRID_E = (EE + 255) / 256;    // 1954
    const int NBLK_SCAN = (NN + 255) / 256; // 196

    // 1) feature encoder
    fe_mlp_k<<<(NN + 255) / 256, 256>>>(feat, fe_W0, fe_b0, fe_W1, fe_b1, p_h, p_feats);

    // 2) CSR by dst (parallel scan)
    zero_int_k<<<NBLK_SCAN, 256>>>(p_deg, NN);
    hist_k<<<GRID_E, 256>>>(dst, p_deg);
    scan_partial_k<<<NBLK_SCAN, 256>>>(p_deg, p_bsum);
    scan_bsum_k<<<1, 256>>>(p_bsum, NBLK_SCAN);
    scan_final_k<<<NBLK_SCAN, 256>>>(p_deg, p_bsum, p_rowptr, p_cursor);
    scatter_k<<<GRID_E, 256>>>(dst, p_cursor, p_eidx);

    // 3) EGAT layers
    for (int l = 0; l < 3; l++) {
        precompute_fij_k<<<222, 128>>>(etype_emb, rid_emb, rc_W, rp_W, rc_b, rp_b,
                                       W_fij + l * 64 * 128, egat_bias + l * 128,
                                       p_table, p_crcrp);
        proj3_k<<<dim3(GRID_N, 3), 256, SH_PROJ>>>(
            p_h, W_ni + l * 64 * 128, W_nj + l * 64 * 128, W_node + l * 64 * 128,
            p_hni, p_hnj, p_hnode, NN);

        edge_attn_k<<<EE / 8, 256>>>(p_hni, p_hnj, p_table, p_crcrp,
                                     attn + l * 128, att_rc, att_rp,
                                     src, dst, etype, rid, p_e);

        softmax_agg_k<<<NN / 8, 256>>>(p_e, p_rowptr, p_eidx, src, p_hnode, p_hatt);

        mlp_fused_k<<<GRID_N, 256, SH_MLP>>>(
            p_hatt, Wm0 + l * 128 * 128, bm0 + l * 128,
            Wm1 + l * 128 * 64, bm1 + l * 64,
            p_h, p_feats, 64 * (l + 1), NN);
    }

    // 4) pooling (2-stage) + output
    pool_part_k<<<dim3(NB, 5, NSPLIT), 256>>>(p_feats, p_pool);
    pool_reduce_k<<<dim3(NB, 5), 64>>>(p_pool, p_gmax);
    long long total = (long long)NB * NPG * 532;
    write_out_k<<<(int)((total + 255) / 256), 256>>>(p_feats, p_gmax, out);
}

// round 14
// speedup vs baseline: 1.3831x; 1.1792x over previous
#include <cuda_runtime.h>
#include <cuda_bf16.h>
#include <cstdint>
#include <cstddef>

// ---------------- problem constants ----------------
#define NN     50000
#define EE     500000
#define NPG    6250
#define NB     8
#define FSTR   272
#define NSPLIT 13
#define PS     481
// internal feats layout per node: [h0(64) h1(64) h2(64) h3(64) feat(10) pad(6)]

// ---------------- device scratch ----------------
__device__ __align__(16) float g_h     [NN * 64];
__device__ __align__(16) float g_hni   [NN * 128];
__device__ __align__(16) float g_hnj   [NN * 128];
__device__ __align__(16) float g_hnode [NN * 128];
__device__ __align__(16) float g_hatt  [NN * 128];
__device__ __align__(16) float g_feats [NN * FSTR];
__device__ __align__(16) float g_e     [EE * 2];
__device__ int   g_deg   [NN];
__device__ int   g_rowptr[NN + 1];
__device__ int   g_cursor[NN];
__device__ int   g_eidx  [EE];
__device__ int   g_bsum  [256];
__device__ __align__(16) float g_table [217 * 128];
__device__ __align__(16) float g_crcrp [5 * 128];
__device__ __align__(16) float g_gmax  [NB * FSTR];
__device__ __align__(16) float g_pool  [NB * 5 * NSPLIT * 64];

// ---------------- tf32 helpers ----------------
__device__ __forceinline__ uint32_t f2tf(float x) {
    uint32_t r;
    asm("cvt.rna.tf32.f32 %0, %1;" : "=r"(r) : "f"(x));
    return r;
}
__device__ __forceinline__ uint4 f4tf(float4 v) {
    return make_uint4(f2tf(v.x), f2tf(v.y), f2tf(v.z), f2tf(v.w));
}
__device__ __forceinline__ void mma_tf32(float c[4], const uint32_t a[4], const uint32_t b[2]) {
    asm volatile(
        "mma.sync.aligned.m16n8k8.row.col.f32.tf32.tf32.f32 "
        "{%0,%1,%2,%3}, {%4,%5,%6,%7}, {%8,%9}, {%0,%1,%2,%3};"
        : "+f"(c[0]), "+f"(c[1]), "+f"(c[2]), "+f"(c[3])
        : "r"(a[0]), "r"(a[1]), "r"(a[2]), "r"(a[3]), "r"(b[0]), "r"(b[1]));
}

// ---------------- feature-encoder MLP (feat -> h0) ----------------
__global__ __launch_bounds__(256) void fe_mlp_k(
    const float* __restrict__ feat, const float* __restrict__ W0,
    const float* __restrict__ b0,   const float* __restrict__ W1,
    const float* __restrict__ b1,   float* __restrict__ h,
    float* __restrict__ feats)
{
    __shared__ float sW0[640], sb0[64], sW1[4096], sb1[64];
    int tid = threadIdx.x;
    for (int i = tid; i < 640;  i += 256) sW0[i] = W0[i];
    for (int i = tid; i < 4096; i += 256) sW1[i] = W1[i];
    if (tid < 64) { sb0[tid] = b0[tid]; sb1[tid] = b1[tid]; }
    __syncthreads();
    int n = blockIdx.x * 256 + tid;
    if (n >= NN) return;
    float f[10];
#pragma unroll
    for (int i = 0; i < 10; i++) {
        f[i] = feat[n * 10 + i];
        feats[(size_t)n * FSTR + 256 + i] = f[i];
    }
    float hid[64];
#pragma unroll
    for (int c = 0; c < 64; c++) {
        float s = sb0[c];
#pragma unroll
        for (int k = 0; k < 10; k++) s += f[k] * sW0[k * 64 + c];
        hid[c] = fmaxf(s, 0.f);
    }
    for (int c = 0; c < 64; c++) {
        float s = sb1[c];
#pragma unroll
        for (int k = 0; k < 64; k++) s += hid[k] * sW1[k * 64 + c];
        h[(size_t)n * 64 + c] = s;
        feats[(size_t)n * FSTR + c] = s;
    }
}

// ---------------- CSR build ----------------
__global__ void zero_int_k(int* p, int n) {
    int i = blockIdx.x * 256 + threadIdx.x;
    if (i < n) p[i] = 0;
}
__global__ void hist_k(const int* __restrict__ dst, int* deg) {
    int e = blockIdx.x * 256 + threadIdx.x;
    if (e < EE) atomicAdd(&deg[dst[e]], 1);
}
__global__ void scan_partial_k(const int* __restrict__ deg, int* bsum) {
    __shared__ int s[256];
    int i = blockIdx.x * 256 + threadIdx.x;
    s[threadIdx.x] = (i < NN) ? deg[i] : 0;
    __syncthreads();
#pragma unroll
    for (int o = 128; o; o >>= 1) {
        if (threadIdx.x < o) s[threadIdx.x] += s[threadIdx.x + o];
        __syncthreads();
    }
    if (threadIdx.x == 0) bsum[blockIdx.x] = s[0];
}
__global__ void scan_bsum_k(int* bsum, int nb) {
    __shared__ int s[256];
    int t = threadIdx.x;
    int v = (t < nb) ? bsum[t] : 0;
    s[t] = v;
    __syncthreads();
#pragma unroll
    for (int o = 1; o < 256; o <<= 1) {
        int x = (t >= o) ? s[t - o] : 0;
        __syncthreads();
        s[t] += x;
        __syncthreads();
    }
    if (t < nb) bsum[t] = s[t] - v;   // exclusive
}
__global__ void scan_final_k(const int* __restrict__ deg, const int* __restrict__ bsum,
                             int* rowptr, int* cursor) {
    __shared__ int s[256];
    int i = blockIdx.x * 256 + threadIdx.x;
    int v = (i < NN) ? deg[i] : 0;
    s[threadIdx.x] = v;
    __syncthreads();
#pragma unroll
    for (int o = 1; o < 256; o <<= 1) {
        int x = (threadIdx.x >= o) ? s[threadIdx.x - o] : 0;
        __syncthreads();
        s[threadIdx.x] += x;
        __syncthreads();
    }
    if (i < NN) {
        int off = bsum[blockIdx.x] + s[threadIdx.x] - v;
        rowptr[i] = off;
        cursor[i] = off;
    }
    if (i == NN - 1) rowptr[NN] = EE;
}
__global__ void scatter_k(const int* __restrict__ dst, int* cursor, int* eidx) {
    int e = blockIdx.x * 256 + threadIdx.x;
    if (e < EE) {
        int pos = atomicAdd(&cursor[dst[e]], 1);
        eidx[pos] = e;
    }
}

// ---------------- per-layer f_fij precompute ----------------
__global__ void precompute_fij_k(
    const float* __restrict__ etype_emb, const float* __restrict__ rid_emb,
    const float* __restrict__ rc_W, const float* __restrict__ rp_W,
    const float* __restrict__ rc_b, const float* __restrict__ rp_b,
    const float* __restrict__ Wf,   const float* __restrict__ ebias,
    float* __restrict__ table, float* __restrict__ crcrp)
{
    int row = blockIdx.x;         // 0..221
    int c   = threadIdx.x;        // 0..127
    __shared__ float v[64];
    if (threadIdx.x < 64) {
        int k = threadIdx.x;
        float val;
        if (row < 217) {
            int et = row / 31, r = row % 31;
            val = etype_emb[et * 64 + k] + rid_emb[r * 64 + k] + rc_b[k] + rp_b[k];
        } else if (row < 219) {
            val = rc_W[(row - 217) * 64 + k];
        } else {
            val = rp_W[(row - 219) * 64 + k];
        }
        v[k] = val;
    }
    __syncthreads();
    float s = 0.f;
#pragma unroll
    for (int k = 0; k < 64; k++) s += v[k] * Wf[k * 128 + c];
    if (row < 217) table[row * 128 + c] = s + ebias[c];
    else           crcrp[(row - 217) * 128 + c] = s;
}

// ---------------- tf32 3-way projection GEMM: [128,64] tile @ [64,128] ------
// grid (nblk, 3); 8 warps. Warp w: m0=(w&3)*32 (2 m16 tiles), n0=(w>>2)*64 (8 n8 tiles).
#define LDA_P 68
#define LDW_P 132
__global__ __launch_bounds__(256) void proj3_k(
    const float* __restrict__ A,
    const float* __restrict__ W0, const float* __restrict__ W1, const float* __restrict__ W2,
    float* __restrict__ C0, float* __restrict__ C1, float* __restrict__ C2,
    int nrows)
{
    const float* W = (blockIdx.y == 0) ? W0 : (blockIdx.y == 1) ? W1 : W2;
    float*       C = (blockIdx.y == 0) ? C0 : (blockIdx.y == 1) ? C1 : C2;
    extern __shared__ uint32_t smu[];
    uint32_t* As = smu;                 // [128][LDA_P]
    uint32_t* Ws = smu + 128 * LDA_P;   // [64][LDW_P]
    int tid  = threadIdx.x;
    int row0 = blockIdx.x * 128;
    // load A tile 128x64 (2048 float4)
#pragma unroll
    for (int i = 0; i < 8; i++) {
        int idx = tid + i * 256;
        int r = idx >> 4, c4 = idx & 15;
        float4 v = make_float4(0.f, 0.f, 0.f, 0.f);
        if (row0 + r < nrows) v = *(const float4*)(A + (size_t)(row0 + r) * 64 + c4 * 4);
        *(uint4*)(As + r * LDA_P + c4 * 4) = f4tf(v);
    }
    // load W 64x128 (2048 float4)
#pragma unroll
    for (int i = 0; i < 8; i++) {
        int idx = tid + i * 256;
        int r = idx >> 5, c4 = idx & 31;
        *(uint4*)(Ws + r * LDW_P + c4 * 4) = f4tf(*(const float4*)(W + idx * 4));
    }
    __syncthreads();
    int w = tid >> 5, lane = tid & 31;
    int gr = lane >> 2, gc = lane & 3;
    int m0 = (w & 3) * 32, n0 = (w >> 2) * 64;
    float acc[2][8][4];
#pragma unroll
    for (int mt = 0; mt < 2; mt++)
#pragma unroll
        for (int nt = 0; nt < 8; nt++)
            acc[mt][nt][0] = acc[mt][nt][1] = acc[mt][nt][2] = acc[mt][nt][3] = 0.f;
#pragma unroll
    for (int kt = 0; kt < 8; kt++) {
        int k0 = kt * 8;
        uint32_t a[2][4], b[8][2];
#pragma unroll
        for (int mt = 0; mt < 2; mt++) {
            int rb = m0 + mt * 16 + gr;
            a[mt][0] = As[rb * LDA_P + k0 + gc];
            a[mt][1] = As[(rb + 8) * LDA_P + k0 + gc];
            a[mt][2] = As[rb * LDA_P + k0 + gc + 4];
            a[mt][3] = As[(rb + 8) * LDA_P + k0 + gc + 4];
        }
#pragma unroll
        for (int nt = 0; nt < 8; nt++) {
            int cb = n0 + nt * 8 + gr;
            b[nt][0] = Ws[(k0 + gc) * LDW_P + cb];
            b[nt][1] = Ws[(k0 + gc + 4) * LDW_P + cb];
        }
#pragma unroll
        for (int mt = 0; mt < 2; mt++)
#pragma unroll
            for (int nt = 0; nt < 8; nt++)
                mma_tf32(acc[mt][nt], a[mt], b[nt]);
    }
#pragma unroll
    for (int mt = 0; mt < 2; mt++) {
        int r  = row0 + m0 + mt * 16 + gr;
        int r8 = r + 8;
#pragma unroll
        for (int nt = 0; nt < 8; nt++) {
            int c = n0 + nt * 8 + 2 * gc;
            if (r < nrows)
                *(float2*)(C + (size_t)r * 128 + c)  = make_float2(acc[mt][nt][0], acc[mt][nt][1]);
            if (r8 < nrows)
                *(float2*)(C + (size_t)r8 * 128 + c) = make_float2(acc[mt][nt][2], acc[mt][nt][3]);
        }
    }
}

// ---------------- tf32 fused node MLP: h = relu(hatt@Wm0+bm0)@Wm1+bm1 + h ---
#define LDH_M 132
#define LDW2_M 68
__global__ __launch_bounds__(256) void mlp_fused_k(
    const float* __restrict__ hatt,
    const float* __restrict__ Wm0, const float* __restrict__ bm0,
    const float* __restrict__ Wm1, const float* __restrict__ bm1,
    float* __restrict__ h, float* __restrict__ feats, int foff, int nrows)
{
    extern __shared__ uint32_t smu[];
    uint32_t* As = smu;                 // [128][LDH_M] : hatt, then Hs
    uint32_t* Ws = smu + 128 * LDH_M;   // [128][LDH_M] for Wm0; [128][LDW2_M] for Wm1
    int tid  = threadIdx.x;
    int row0 = blockIdx.x * 128;
#pragma unroll
    for (int i = 0; i < 16; i++) {
        int idx = tid + i * 256;
        int r = idx >> 5, c4 = idx & 31;
        float4 v = make_float4(0.f, 0.f, 0.f, 0.f);
        if (row0 + r < nrows) v = *(const float4*)(hatt + (size_t)(row0 + r) * 128 + c4 * 4);
        *(uint4*)(As + r * LDH_M + c4 * 4) = f4tf(v);
    }
#pragma unroll
    for (int i = 0; i < 16; i++) {
        int idx = tid + i * 256;
        int r = idx >> 5, c4 = idx & 31;
        *(uint4*)(Ws + r * LDH_M + c4 * 4) = f4tf(*(const float4*)(Wm0 + idx * 4));
    }
    __syncthreads();
    int w = tid >> 5, lane = tid & 31;
    int gr = lane >> 2, gc = lane & 3;
    int m0 = (w & 3) * 32;
    // ---- GEMM1: K=128, N=128 ----
    {
        int n0 = (w >> 2) * 64;
        float acc[2][8][4];
#pragma unroll
        for (int mt = 0; mt < 2; mt++)
#pragma unroll
            for (int nt = 0; nt < 8; nt++)
                acc[mt][nt][0] = acc[mt][nt][1] = acc[mt][nt][2] = acc[mt][nt][3] = 0.f;
#pragma unroll
        for (int kt = 0; kt < 16; kt++) {
            int k0 = kt * 8;
            uint32_t a[2][4], b[8][2];
#pragma unroll
            for (int mt = 0; mt < 2; mt++) {
                int rb = m0 + mt * 16 + gr;
                a[mt][0] = As[rb * LDH_M + k0 + gc];
                a[mt][1] = As[(rb + 8) * LDH_M + k0 + gc];
                a[mt][2] = As[rb * LDH_M + k0 + gc + 4];
                a[mt][3] = As[(rb + 8) * LDH_M + k0 + gc + 4];
            }
#pragma unroll
            for (int nt = 0; nt < 8; nt++) {
                int cb = n0 + nt * 8 + gr;
                b[nt][0] = Ws[(k0 + gc) * LDH_M + cb];
                b[nt][1] = Ws[(k0 + gc + 4) * LDH_M + cb];
            }
#pragma unroll
            for (int mt = 0; mt < 2; mt++)
#pragma unroll
                for (int nt = 0; nt < 8; nt++)
                    mma_tf32(acc[mt][nt], a[mt], b[nt]);
        }
        __syncthreads();   // all As/Ws reads done; safe to overwrite
        // epilogue1: +bm0, relu, Hs (tf32) back into As
#pragma unroll
        for (int mt = 0; mt < 2; mt++) {
            int rb  = m0 + mt * 16 + gr;
#pragma unroll
            for (int nt = 0; nt < 8; nt++) {
                int c = n0 + nt * 8 + 2 * gc;
                float b0v = bm0[c], b1v = bm0[c + 1];
                As[rb * LDH_M + c]           = f2tf(fmaxf(acc[mt][nt][0] + b0v, 0.f));
                As[rb * LDH_M + c + 1]       = f2tf(fmaxf(acc[mt][nt][1] + b1v, 0.f));
                As[(rb + 8) * LDH_M + c]     = f2tf(fmaxf(acc[mt][nt][2] + b0v, 0.f));
                As[(rb + 8) * LDH_M + c + 1] = f2tf(fmaxf(acc[mt][nt][3] + b1v, 0.f));
            }
        }
    }
    // load Wm1 [128][64] into Ws (stride LDW2_M)
#pragma unroll
    for (int i = 0; i < 8; i++) {
        int idx = tid + i * 256;
        int r = idx >> 4, c4 = idx & 15;
        *(uint4*)(Ws + r * LDW2_M + c4 * 4) = f4tf(*(const float4*)(Wm1 + idx * 4));
    }
    __syncthreads();
    // ---- GEMM2: K=128, N=64 ----
    {
        int n0 = (w >> 2) * 32;
        float acc[2][4][4];
#pragma unroll
        for (int mt = 0; mt < 2; mt++)
#pragma unroll
            for (int nt = 0; nt < 4; nt++)
                acc[mt][nt][0] = acc[mt][nt][1] = acc[mt][nt][2] = acc[mt][nt][3] = 0.f;
#pragma unroll
        for (int kt = 0; kt < 16; kt++) {
            int k0 = kt * 8;
            uint32_t a[2][4], b[4][2];
#pragma unroll
            for (int mt = 0; mt < 2; mt++) {
                int rb = m0 + mt * 16 + gr;
                a[mt][0] = As[rb * LDH_M + k0 + gc];
                a[mt][1] = As[(rb + 8) * LDH_M + k0 + gc];
                a[mt][2] = As[rb * LDH_M + k0 + gc + 4];
                a[mt][3] = As[(rb + 8) * LDH_M + k0 + gc + 4];
            }
#pragma unroll
            for (int nt = 0; nt < 4; nt++) {
                int cb = n0 + nt * 8 + gr;
                b[nt][0] = Ws[(k0 + gc) * LDW2_M + cb];
                b[nt][1] = Ws[(k0 + gc + 4) * LDW2_M + cb];
            }
#pragma unroll
            for (int mt = 0; mt < 2; mt++)
#pragma unroll
                for (int nt = 0; nt < 4; nt++)
                    mma_tf32(acc[mt][nt], a[mt], b[nt]);
        }
        // epilogue2: +bm1 + residual, store h and feats
#pragma unroll
        for (int mt = 0; mt < 2; mt++) {
            int r  = row0 + m0 + mt * 16 + gr;
            int r8 = r + 8;
#pragma unroll
            for (int nt = 0; nt < 4; nt++) {
                int c = n0 + nt * 8 + 2 * gc;
                float b0v = bm1[c], b1v = bm1[c + 1];
                if (r < nrows) {
                    float2 prev = *(const float2*)(h + (size_t)r * 64 + c);
                    float2 o = make_float2(acc[mt][nt][0] + b0v + prev.x,
                                           acc[mt][nt][1] + b1v + prev.y);
                    *(float2*)(h + (size_t)r * 64 + c) = o;
                    *(float2*)(feats + (size_t)r * FSTR + foff + c) = o;
                }
                if (r8 < nrows) {
                    float2 prev = *(const float2*)(h + (size_t)r8 * 64 + c);
                    float2 o = make_float2(acc[mt][nt][2] + b0v + prev.x,
                                           acc[mt][nt][3] + b1v + prev.y);
                    *(float2*)(h + (size_t)r8 * 64 + c) = o;
                    *(float2*)(feats + (size_t)r8 * FSTR + foff + c) = o;
                }
            }
        }
    }
}

// ---------------- edge attention logits (warp per edge) ----------------
__global__ __launch_bounds__(256) void edge_attn_k(
    const float* __restrict__ hni, const float* __restrict__ hnj,
    const float* __restrict__ table, const float* __restrict__ crcrp,
    const float* __restrict__ attn,
    const float* __restrict__ att_rc, const float* __restrict__ att_rp,
    const int* __restrict__ src, const int* __restrict__ dst,
    const int* __restrict__ etype, const int* __restrict__ rid,
    float* __restrict__ e_out)
{
    __shared__ float sC[640], sAttn[128];
    for (int i = threadIdx.x; i < 640; i += 256) sC[i] = crcrp[i];
    for (int i = threadIdx.x; i < 128; i += 256) sAttn[i] = attn[i];
    __syncthreads();
    int edge = blockIdx.x * 8 + (threadIdx.x >> 5);
    if (edge >= EE) return;
    int lane = threadIdx.x & 31;
    int s = src[edge], d = dst[edge];
    int tr = etype[edge] * 31 + rid[edge];
    float a0 = att_rc[edge * 2], a1 = att_rc[edge * 2 + 1];
    float p0 = att_rp[edge * 3], p1 = att_rp[edge * 3 + 1], p2 = att_rp[edge * 3 + 2];
    int c4 = lane * 4;
    float4 fi = *(const float4*)(hni + (size_t)s * 128 + c4);
    float4 fj = *(const float4*)(hnj + (size_t)d * 128 + c4);
    float4 ft = *(const float4*)(table + (size_t)tr * 128 + c4);
    float fiv[4] = {fi.x, fi.y, fi.z, fi.w};
    float fjv[4] = {fj.x, fj.y, fj.z, fj.w};
    float ftv[4] = {ft.x, ft.y, ft.z, ft.w};
    float acc = 0.f;
#pragma unroll
    for (int j = 0; j < 4; j++) {
        int c = c4 + j;
        float x = fiv[j] + fjv[j] + ftv[j]
                + a0 * sC[c]       + a1 * sC[128 + c]
                + p0 * sC[256 + c] + p1 * sC[384 + c] + p2 * sC[512 + c];
        x = (x >= 0.f) ? x : 0.2f * x;
        acc += x * sAttn[c];
    }
    acc += __shfl_xor_sync(0xffffffffu, acc, 8);
    acc += __shfl_xor_sync(0xffffffffu, acc, 4);
    acc += __shfl_xor_sync(0xffffffffu, acc, 2);
    acc += __shfl_xor_sync(0xffffffffu, acc, 1);
    if ((lane & 15) == 0) e_out[(size_t)edge * 2 + (lane >> 4)] = acc;
}

// ---------------- segment softmax + aggregation (warp per dst node) ----------
__global__ __launch_bounds__(256) void softmax_agg_k(
    const float* __restrict__ e_log, const int* __restrict__ rowptr,
    const int* __restrict__ eidx, const int* __restrict__ src,
    const float* __restrict__ hnode, float* __restrict__ hatt)
{
    int warp = threadIdx.x >> 5, lane = threadIdx.x & 31;
    int node = blockIdx.x * 8 + warp;
    if (node >= NN) return;
    int i0 = rowptr[node], i1 = rowptr[node + 1];
    float4 acc = make_float4(0.f, 0.f, 0.f, 0.f);
    if (i1 > i0) {
        float m0 = -1e30f, m1 = -1e30f, s0 = 0.f, s1 = 0.f;
        for (int i = i0 + lane; i < i1; i += 32) {
            int idx = eidx[i];
            float2 ev = *(const float2*)(e_log + (size_t)idx * 2);
            float n0 = fmaxf(m0, ev.x);
            s0 = s0 * __expf(m0 - n0) + __expf(ev.x - n0);
            m0 = n0;
            float n1 = fmaxf(m1, ev.y);
            s1 = s1 * __expf(m1 - n1) + __expf(ev.y - n1);
            m1 = n1;
        }
#pragma unroll
        for (int o = 16; o; o >>= 1) {
            float mo0 = __shfl_xor_sync(0xffffffffu, m0, o);
            float so0 = __shfl_xor_sync(0xffffffffu, s0, o);
            float mn0 = fmaxf(m0, mo0);
            s0 = s0 * __expf(m0 - mn0) + so0 * __expf(mo0 - mn0);
            m0 = mn0;
            float mo1 = __shfl_xor_sync(0xffffffffu, m1, o);
            float so1 = __shfl_xor_sync(0xffffffffu, s1, o);
            float mn1 = fmaxf(m1, mo1);
            s1 = s1 * __expf(m1 - mn1) + so1 * __expf(mo1 - mn1);
            m1 = mn1;
        }
        int head = lane >> 4;
        float mh   = head ? m1 : m0;
        float invh = 1.f / ((head ? s1 : s0) + 1e-9f);
        int c4 = lane * 4;
        int idx = eidx[i0];
        for (int i = i0; i < i1; i++) {
            int idx_n = (i + 1 < i1) ? eidx[i + 1] : 0;
            int sn = src[idx];
            float el = e_log[(size_t)idx * 2 + head];
            float4 v = *(const float4*)(hnode + (size_t)sn * 128 + c4);
            float alpha = __expf(el - mh) * invh;
            acc.x += alpha * v.x; acc.y += alpha * v.y;
            acc.z += alpha * v.z; acc.w += alpha * v.w;
            idx = idx_n;
        }
    }
    *(float4*)(hatt + (size_t)node * 128 + lane * 4) = acc;
}

// ---------------- graph max pooling (2-stage) + output assembly --------------
__global__ void pool_part_k(const float* __restrict__ feats, float* __restrict__ part) {
    int b = blockIdx.x, fc = blockIdx.y, sp = blockIdx.z;
    int fl = threadIdx.x & 63;
    int f  = fc * 64 + fl;
    int grp = threadIdx.x >> 6;
    int n0 = sp * PS, n1 = n0 + PS;
    if (n1 > NPG) n1 = NPG;
    float m = -1e30f;
    if (f < 266) {
        const float* base = feats + (size_t)b * NPG * FSTR;
        for (int n = n0 + grp; n < n1; n += 4)
            m = fmaxf(m, base[(size_t)n * FSTR + f]);
    }
    __shared__ float sm[256];
    sm[threadIdx.x] = m;
    __syncthreads();
    if (grp == 0) {
        m = fmaxf(fmaxf(sm[threadIdx.x], sm[threadIdx.x + 64]),
                  fmaxf(sm[threadIdx.x + 128], sm[threadIdx.x + 192]));
        part[((b * 5 + fc) * NSPLIT + sp) * 64 + fl] = m;
    }
}
__global__ void pool_reduce_k(const float* __restrict__ part, float* __restrict__ gmax) {
    int b = blockIdx.x, fc = blockIdx.y, t = threadIdx.x;   // block 64
    float m = -1e30f;
#pragma unroll
    for (int sp = 0; sp < NSPLIT; sp++)
        m = fmaxf(m, part[((b * 5 + fc) * NSPLIT + sp) * 64 + t]);
    int f = fc * 64 + t;
    if (f < 266) gmax[b * FSTR + f] = m;
}

__global__ void write_out_k(const float* __restrict__ feats,
                            const float* __restrict__ gmax,
                            float* __restrict__ out) {
    long long idx = (long long)blockIdx.x * 256 + threadIdx.x;
    const long long total = (long long)NB * NPG * 532;
    if (idx >= total) return;
    int c = (int)(idx % 532);
    long long bn = idx / 532;
    int b = (int)(bn / NPG);
    int cl = (c < 266) ? c : (c - 266);
    int ci = (cl < 10) ? (256 + cl) : (cl - 10);
    out[idx] = (c < 266) ? feats[bn * FSTR + ci] : gmax[b * FSTR + ci];
}

// ---------------- host launcher ----------------
extern "C" void kernel_launch(void* const* d_in, const int* in_sizes, int n_in,
                              void* d_out, int out_size)
{
    const float* feat      = (const float*)d_in[0];
    const float* att_rc    = (const float*)d_in[1];
    const float* att_rp    = (const float*)d_in[2];
    const float* etype_emb = (const float*)d_in[3];
    const float* rid_emb   = (const float*)d_in[4];
    const float* rc_W      = (const float*)d_in[5];
    const float* rc_b      = (const float*)d_in[6];
    const float* rp_W      = (const float*)d_in[7];
    const float* rp_b      = (const float*)d_in[8];
    const float* fe_W0     = (const float*)d_in[9];
    const float* fe_b0     = (const float*)d_in[10];
    const float* fe_W1     = (const float*)d_in[11];
    const float* fe_b1     = (const float*)d_in[12];
    const float* W_ni      = (const float*)d_in[13];
    const float* W_nj      = (const float*)d_in[14];
    const float* W_fij     = (const float*)d_in[15];
    const float* W_node    = (const float*)d_in[16];
    const float* attn      = (const float*)d_in[17];
    const float* egat_bias = (const float*)d_in[18];
    const float* Wm0       = (const float*)d_in[19];
    const float* bm0       = (const float*)d_in[20];
    const float* Wm1       = (const float*)d_in[21];
    const float* bm1       = (const float*)d_in[22];
    const int*   src       = (const int*)d_in[23];
    const int*   dst       = (const int*)d_in[24];
    const int*   etype     = (const int*)d_in[25];
    const int*   rid       = (const int*)d_in[26];
    float* out = (float*)d_out;

    float *p_h, *p_hni, *p_hnj, *p_hnode, *p_hatt, *p_feats, *p_e;
    float *p_table, *p_crcrp, *p_gmax, *p_pool;
    int *p_deg, *p_rowptr, *p_cursor, *p_eidx, *p_bsum;
    cudaGetSymbolAddress((void**)&p_h,      g_h);
    cudaGetSymbolAddress((void**)&p_hni,    g_hni);
    cudaGetSymbolAddress((void**)&p_hnj,    g_hnj);
    cudaGetSymbolAddress((void**)&p_hnode,  g_hnode);
    cudaGetSymbolAddress((void**)&p_hatt,   g_hatt);
    cudaGetSymbolAddress((void**)&p_feats,  g_feats);
    cudaGetSymbolAddress((void**)&p_e,      g_e);
    cudaGetSymbolAddress((void**)&p_table,  g_table);
    cudaGetSymbolAddress((void**)&p_crcrp,  g_crcrp);
    cudaGetSymbolAddress((void**)&p_gmax,   g_gmax);
    cudaGetSymbolAddress((void**)&p_pool,   g_pool);
    cudaGetSymbolAddress((void**)&p_deg,    g_deg);
    cudaGetSymbolAddress((void**)&p_rowptr, g_rowptr);
    cudaGetSymbolAddress((void**)&p_cursor, g_cursor);
    cudaGetSymbolAddress((void**)&p_eidx,   g_eidx);
    cudaGetSymbolAddress((void**)&p_bsum,   g_bsum);

    const int SH_PROJ = (128 * LDA_P + 64 * LDW_P) * 4;    // ~68.6 KB
    const int SH_MLP  = (128 * LDH_M * 2) * 4;             // ~135 KB
    cudaFuncSetAttribute((const void*)proj3_k,
                         cudaFuncAttributeMaxDynamicSharedMemorySize, SH_PROJ);
    cudaFuncSetAttribute((const void*)mlp_fused_k,
                         cudaFuncAttributeMaxDynamicSharedMemorySize, SH_MLP);

    const int GRID_T = (NN + 127) / 128;    // 391 (tf32 tiles)
    const int GRID_E = (EE + 255) / 256;    // 1954
    const int NBLK_SCAN = (NN + 255) / 256; // 196

    // 1) feature encoder
    fe_mlp_k<<<(NN + 255) / 256, 256>>>(feat, fe_W0, fe_b0, fe_W1, fe_b1, p_h, p_feats);

    // 2) CSR by dst (parallel scan)
    zero_int_k<<<NBLK_SCAN, 256>>>(p_deg, NN);
    hist_k<<<GRID_E, 256>>>(dst, p_deg);
    scan_partial_k<<<NBLK_SCAN, 256>>>(p_deg, p_bsum);
    scan_bsum_k<<<1, 256>>>(p_bsum, NBLK_SCAN);
    scan_final_k<<<NBLK_SCAN, 256>>>(p_deg, p_bsum, p_rowptr, p_cursor);
    scatter_k<<<GRID_E, 256>>>(dst, p_cursor, p_eidx);

    // 3) EGAT layers
    for (int l = 0; l < 3; l++) {
        precompute_fij_k<<<222, 128>>>(etype_emb, rid_emb, rc_W, rp_W, rc_b, rp_b,
                                       W_fij + l * 64 * 128, egat_bias + l * 128,
                                       p_table, p_crcrp);
        proj3_k<<<dim3(GRID_T, 3), 256, SH_PROJ>>>(
            p_h, W_ni + l * 64 * 128, W_nj + l * 64 * 128, W_node + l * 64 * 128,
            p_hni, p_hnj, p_hnode, NN);

        edge_attn_k<<<EE / 8, 256>>>(p_hni, p_hnj, p_table, p_crcrp,
                                     attn + l * 128, att_rc, att_rp,
                                     src, dst, etype, rid, p_e);

        softmax_agg_k<<<NN / 8, 256>>>(p_e, p_rowptr, p_eidx, src, p_hnode, p_hatt);

        mlp_fused_k<<<GRID_T, 256, SH_MLP>>>(
            p_hatt, Wm0 + l * 128 * 128, bm0 + l * 128,
            Wm1 + l * 128 * 64, bm1 + l * 64,
            p_h, p_feats, 64 * (l + 1), NN);
    }

    // 4) pooling (2-stage) + output
    pool_part_k<<<dim3(NB, 5, NSPLIT), 256>>>(p_feats, p_pool);
    pool_reduce_k<<<dim3(NB, 5), 64>>>(p_pool, p_gmax);
    long long total = (long long)NB * NPG * 532;
    write_out_k<<<(int)((total + 255) / 256), 256>>>(p_feats, p_gmax, out);
}

// round 15
// speedup vs baseline: 1.3972x; 1.0102x over previous
#include <cuda_runtime.h>
#include <cuda_bf16.h>
#include <cstdint>
#include <cstddef>

// ---------------- problem constants ----------------
#define NN     50000
#define EE     500000
#define NPG    6250
#define NB     8
#define FSTR   272
#define NSPLIT 13
#define PS     481
// internal feats layout per node: [h0(64) h1(64) h2(64) h3(64) feat(10) pad(6)]

// ---------------- device scratch ----------------
__device__ __align__(16) float g_h     [NN * 64];
__device__ __align__(16) float g_hni   [NN * 128];
__device__ __align__(16) float g_hnj   [NN * 128];
__device__ __align__(16) float g_hnode [NN * 128];
__device__ __align__(16) float g_hatt  [NN * 128];
__device__ __align__(16) float g_feats [NN * FSTR];
__device__ __align__(16) float g_e     [EE * 2];
__device__ int   g_deg   [NN];
__device__ int   g_rowptr[NN + 1];
__device__ int   g_cursor[NN];
__device__ int   g_eidx  [EE];
__device__ int   g_bsum  [256];
__device__ __align__(16) float g_table [217 * 128];
__device__ __align__(16) float g_crcrp [5 * 128];
__device__ __align__(16) float g_gmax  [NB * FSTR];
__device__ __align__(16) float g_pool  [NB * 5 * NSPLIT * 64];

// ---------------- tf32 helpers ----------------
__device__ __forceinline__ uint32_t f2tf(float x) {
    uint32_t r;
    asm("cvt.rna.tf32.f32 %0, %1;" : "=r"(r) : "f"(x));
    return r;
}
__device__ __forceinline__ uint4 f4tf(float4 v) {
    return make_uint4(f2tf(v.x), f2tf(v.y), f2tf(v.z), f2tf(v.w));
}
__device__ __forceinline__ void mma_tf32(float c[4], const uint32_t a[4], const uint32_t b[2]) {
    asm volatile(
        "mma.sync.aligned.m16n8k8.row.col.f32.tf32.tf32.f32 "
        "{%0,%1,%2,%3}, {%4,%5,%6,%7}, {%8,%9}, {%0,%1,%2,%3};"
        : "+f"(c[0]), "+f"(c[1]), "+f"(c[2]), "+f"(c[3])
        : "r"(a[0]), "r"(a[1]), "r"(a[2]), "r"(a[3]), "r"(b[0]), "r"(b[1]));
}

// ---------------- feature-encoder MLP (feat -> h0) ----------------
__global__ __launch_bounds__(256) void fe_mlp_k(
    const float* __restrict__ feat, const float* __restrict__ W0,
    const float* __restrict__ b0,   const float* __restrict__ W1,
    const float* __restrict__ b1,   float* __restrict__ h,
    float* __restrict__ feats)
{
    __shared__ float sW0[640], sb0[64], sW1[4096], sb1[64];
    int tid = threadIdx.x;
    for (int i = tid; i < 640;  i += 256) sW0[i] = W0[i];
    for (int i = tid; i < 4096; i += 256) sW1[i] = W1[i];
    if (tid < 64) { sb0[tid] = b0[tid]; sb1[tid] = b1[tid]; }
    __syncthreads();
    int n = blockIdx.x * 256 + tid;
    if (n >= NN) return;
    float f[10];
#pragma unroll
    for (int i = 0; i < 10; i++) {
        f[i] = feat[n * 10 + i];
        feats[(size_t)n * FSTR + 256 + i] = f[i];
    }
    float hid[64];
#pragma unroll
    for (int c = 0; c < 64; c++) {
        float s = sb0[c];
#pragma unroll
        for (int k = 0; k < 10; k++) s += f[k] * sW0[k * 64 + c];
        hid[c] = fmaxf(s, 0.f);
    }
    for (int c = 0; c < 64; c++) {
        float s = sb1[c];
#pragma unroll
        for (int k = 0; k < 64; k++) s += hid[k] * sW1[k * 64 + c];
        h[(size_t)n * 64 + c] = s;
        feats[(size_t)n * FSTR + c] = s;
    }
}

// ---------------- CSR build ----------------
__global__ void zero_int_k(int* p, int n) {
    int i = blockIdx.x * 256 + threadIdx.x;
    if (i < n) p[i] = 0;
}
__global__ void hist_k(const int* __restrict__ dst, int* deg) {
    int e = blockIdx.x * 256 + threadIdx.x;
    if (e < EE) atomicAdd(&deg[dst[e]], 1);
}
__global__ void scan_partial_k(const int* __restrict__ deg, int* bsum) {
    __shared__ int s[256];
    int i = blockIdx.x * 256 + threadIdx.x;
    s[threadIdx.x] = (i < NN) ? deg[i] : 0;
    __syncthreads();
#pragma unroll
    for (int o = 128; o; o >>= 1) {
        if (threadIdx.x < o) s[threadIdx.x] += s[threadIdx.x + o];
        __syncthreads();
    }
    if (threadIdx.x == 0) bsum[blockIdx.x] = s[0];
}
__global__ void scan_bsum_k(int* bsum, int nb) {
    __shared__ int s[256];
    int t = threadIdx.x;
    int v = (t < nb) ? bsum[t] : 0;
    s[t] = v;
    __syncthreads();
#pragma unroll
    for (int o = 1; o < 256; o <<= 1) {
        int x = (t >= o) ? s[t - o] : 0;
        __syncthreads();
        s[t] += x;
        __syncthreads();
    }
    if (t < nb) bsum[t] = s[t] - v;   // exclusive
}
__global__ void scan_final_k(const int* __restrict__ deg, const int* __restrict__ bsum,
                             int* rowptr, int* cursor) {
    __shared__ int s[256];
    int i = blockIdx.x * 256 + threadIdx.x;
    int v = (i < NN) ? deg[i] : 0;
    s[threadIdx.x] = v;
    __syncthreads();
#pragma unroll
    for (int o = 1; o < 256; o <<= 1) {
        int x = (threadIdx.x >= o) ? s[threadIdx.x - o] : 0;
        __syncthreads();
        s[threadIdx.x] += x;
        __syncthreads();
    }
    if (i < NN) {
        int off = bsum[blockIdx.x] + s[threadIdx.x] - v;
        rowptr[i] = off;
        cursor[i] = off;
    }
    if (i == NN - 1) rowptr[NN] = EE;
}
__global__ void scatter_k(const int* __restrict__ dst, int* cursor, int* eidx) {
    int e = blockIdx.x * 256 + threadIdx.x;
    if (e < EE) {
        int pos = atomicAdd(&cursor[dst[e]], 1);
        eidx[pos] = e;
    }
}

// ---------------- per-layer f_fij precompute ----------------
__global__ void precompute_fij_k(
    const float* __restrict__ etype_emb, const float* __restrict__ rid_emb,
    const float* __restrict__ rc_W, const float* __restrict__ rp_W,
    const float* __restrict__ rc_b, const float* __restrict__ rp_b,
    const float* __restrict__ Wf,   const float* __restrict__ ebias,
    float* __restrict__ table, float* __restrict__ crcrp)
{
    int row = blockIdx.x;         // 0..221
    int c   = threadIdx.x;        // 0..127
    __shared__ float v[64];
    if (threadIdx.x < 64) {
        int k = threadIdx.x;
        float val;
        if (row < 217) {
            int et = row / 31, r = row % 31;
            val = etype_emb[et * 64 + k] + rid_emb[r * 64 + k] + rc_b[k] + rp_b[k];
        } else if (row < 219) {
            val = rc_W[(row - 217) * 64 + k];
        } else {
            val = rp_W[(row - 219) * 64 + k];
        }
        v[k] = val;
    }
    __syncthreads();
    float s = 0.f;
#pragma unroll
    for (int k = 0; k < 64; k++) s += v[k] * Wf[k * 128 + c];
    if (row < 217) table[row * 128 + c] = s + ebias[c];
    else           crcrp[(row - 217) * 128 + c] = s;
}

// ---------------- tf32 3-way projection GEMM: [128,64] tile @ [64,128] ------
// grid (nblk, 3); 8 warps. Warp w: m0=(w&3)*32 (2 m16 tiles), n0=(w>>2)*64 (8 n8 tiles).
#define LDA_P 68
#define LDW_P 132
__global__ __launch_bounds__(256) void proj3_k(
    const float* __restrict__ A,
    const float* __restrict__ W0, const float* __restrict__ W1, const float* __restrict__ W2,
    float* __restrict__ C0, float* __restrict__ C1, float* __restrict__ C2,
    int nrows)
{
    const float* W = (blockIdx.y == 0) ? W0 : (blockIdx.y == 1) ? W1 : W2;
    float*       C = (blockIdx.y == 0) ? C0 : (blockIdx.y == 1) ? C1 : C2;
    extern __shared__ uint32_t smu[];
    uint32_t* As = smu;                 // [128][LDA_P]
    uint32_t* Ws = smu + 128 * LDA_P;   // [64][LDW_P]
    int tid  = threadIdx.x;
    int row0 = blockIdx.x * 128;
    // load A tile 128x64 (2048 float4)
#pragma unroll
    for (int i = 0; i < 8; i++) {
        int idx = tid + i * 256;
        int r = idx >> 4, c4 = idx & 15;
        float4 v = make_float4(0.f, 0.f, 0.f, 0.f);
        if (row0 + r < nrows) v = *(const float4*)(A + (size_t)(row0 + r) * 64 + c4 * 4);
        *(uint4*)(As + r * LDA_P + c4 * 4) = f4tf(v);
    }
    // load W 64x128 (2048 float4)
#pragma unroll
    for (int i = 0; i < 8; i++) {
        int idx = tid + i * 256;
        int r = idx >> 5, c4 = idx & 31;
        *(uint4*)(Ws + r * LDW_P + c4 * 4) = f4tf(*(const float4*)(W + idx * 4));
    }
    __syncthreads();
    int w = tid >> 5, lane = tid & 31;
    int gr = lane >> 2, gc = lane & 3;
    int m0 = (w & 3) * 32, n0 = (w >> 2) * 64;
    float acc[2][8][4];
#pragma unroll
    for (int mt = 0; mt < 2; mt++)
#pragma unroll
        for (int nt = 0; nt < 8; nt++)
            acc[mt][nt][0] = acc[mt][nt][1] = acc[mt][nt][2] = acc[mt][nt][3] = 0.f;
#pragma unroll
    for (int kt = 0; kt < 8; kt++) {
        int k0 = kt * 8;
        uint32_t a[2][4], b[8][2];
#pragma unroll
        for (int mt = 0; mt < 2; mt++) {
            int rb = m0 + mt * 16 + gr;
            a[mt][0] = As[rb * LDA_P + k0 + gc];
            a[mt][1] = As[(rb + 8) * LDA_P + k0 + gc];
            a[mt][2] = As[rb * LDA_P + k0 + gc + 4];
            a[mt][3] = As[(rb + 8) * LDA_P + k0 + gc + 4];
        }
#pragma unroll
        for (int nt = 0; nt < 8; nt++) {
            int cb = n0 + nt * 8 + gr;
            b[nt][0] = Ws[(k0 + gc) * LDW_P + cb];
            b[nt][1] = Ws[(k0 + gc + 4) * LDW_P + cb];
        }
#pragma unroll
        for (int mt = 0; mt < 2; mt++)
#pragma unroll
            for (int nt = 0; nt < 8; nt++)
                mma_tf32(acc[mt][nt], a[mt], b[nt]);
    }
#pragma unroll
    for (int mt = 0; mt < 2; mt++) {
        int r  = row0 + m0 + mt * 16 + gr;
        int r8 = r + 8;
#pragma unroll
        for (int nt = 0; nt < 8; nt++) {
            int c = n0 + nt * 8 + 2 * gc;
            if (r < nrows)
                *(float2*)(C + (size_t)r * 128 + c)  = make_float2(acc[mt][nt][0], acc[mt][nt][1]);
            if (r8 < nrows)
                *(float2*)(C + (size_t)r8 * 128 + c) = make_float2(acc[mt][nt][2], acc[mt][nt][3]);
        }
    }
}

// ---------------- tf32 fused node MLP: h = relu(hatt@Wm0+bm0)@Wm1+bm1 + h ---
#define LDH_M 132
#define LDW2_M 68
__global__ __launch_bounds__(256) void mlp_fused_k(
    const float* __restrict__ hatt,
    const float* __restrict__ Wm0, const float* __restrict__ bm0,
    const float* __restrict__ Wm1, const float* __restrict__ bm1,
    float* __restrict__ h, float* __restrict__ feats, int foff, int nrows)
{
    extern __shared__ uint32_t smu[];
    uint32_t* As = smu;                 // [128][LDH_M] : hatt, then Hs
    uint32_t* Ws = smu + 128 * LDH_M;   // [128][LDH_M] for Wm0; [128][LDW2_M] for Wm1
    int tid  = threadIdx.x;
    int row0 = blockIdx.x * 128;
#pragma unroll
    for (int i = 0; i < 16; i++) {
        int idx = tid + i * 256;
        int r = idx >> 5, c4 = idx & 31;
        float4 v = make_float4(0.f, 0.f, 0.f, 0.f);
        if (row0 + r < nrows) v = *(const float4*)(hatt + (size_t)(row0 + r) * 128 + c4 * 4);
        *(uint4*)(As + r * LDH_M + c4 * 4) = f4tf(v);
    }
#pragma unroll
    for (int i = 0; i < 16; i++) {
        int idx = tid + i * 256;
        int r = idx >> 5, c4 = idx & 31;
        *(uint4*)(Ws + r * LDH_M + c4 * 4) = f4tf(*(const float4*)(Wm0 + idx * 4));
    }
    __syncthreads();
    int w = tid >> 5, lane = tid & 31;
    int gr = lane >> 2, gc = lane & 3;
    int m0 = (w & 3) * 32;
    // ---- GEMM1: K=128, N=128 ----
    {
        int n0 = (w >> 2) * 64;
        float acc[2][8][4];
#pragma unroll
        for (int mt = 0; mt < 2; mt++)
#pragma unroll
            for (int nt = 0; nt < 8; nt++)
                acc[mt][nt][0] = acc[mt][nt][1] = acc[mt][nt][2] = acc[mt][nt][3] = 0.f;
#pragma unroll
        for (int kt = 0; kt < 16; kt++) {
            int k0 = kt * 8;
            uint32_t a[2][4], b[8][2];
#pragma unroll
            for (int mt = 0; mt < 2; mt++) {
                int rb = m0 + mt * 16 + gr;
                a[mt][0] = As[rb * LDH_M + k0 + gc];
                a[mt][1] = As[(rb + 8) * LDH_M + k0 + gc];
                a[mt][2] = As[rb * LDH_M + k0 + gc + 4];
                a[mt][3] = As[(rb + 8) * LDH_M + k0 + gc + 4];
            }
#pragma unroll
            for (int nt = 0; nt < 8; nt++) {
                int cb = n0 + nt * 8 + gr;
                b[nt][0] = Ws[(k0 + gc) * LDH_M + cb];
                b[nt][1] = Ws[(k0 + gc + 4) * LDH_M + cb];
            }
#pragma unroll
            for (int mt = 0; mt < 2; mt++)
#pragma unroll
                for (int nt = 0; nt < 8; nt++)
                    mma_tf32(acc[mt][nt], a[mt], b[nt]);
        }
        __syncthreads();   // all As/Ws reads done; safe to overwrite
        // epilogue1: +bm0, relu, Hs (tf32) back into As
#pragma unroll
        for (int mt = 0; mt < 2; mt++) {
            int rb  = m0 + mt * 16 + gr;
#pragma unroll
            for (int nt = 0; nt < 8; nt++) {
                int c = n0 + nt * 8 + 2 * gc;
                float b0v = bm0[c], b1v = bm0[c + 1];
                As[rb * LDH_M + c]           = f2tf(fmaxf(acc[mt][nt][0] + b0v, 0.f));
                As[rb * LDH_M + c + 1]       = f2tf(fmaxf(acc[mt][nt][1] + b1v, 0.f));
                As[(rb + 8) * LDH_M + c]     = f2tf(fmaxf(acc[mt][nt][2] + b0v, 0.f));
                As[(rb + 8) * LDH_M + c + 1] = f2tf(fmaxf(acc[mt][nt][3] + b1v, 0.f));
            }
        }
    }
    // load Wm1 [128][64] into Ws (stride LDW2_M)
#pragma unroll
    for (int i = 0; i < 8; i++) {
        int idx = tid + i * 256;
        int r = idx >> 4, c4 = idx & 15;
        *(uint4*)(Ws + r * LDW2_M + c4 * 4) = f4tf(*(const float4*)(Wm1 + idx * 4));
    }
    __syncthreads();
    // ---- GEMM2: K=128, N=64 ----
    {
        int n0 = (w >> 2) * 32;
        float acc[2][4][4];
#pragma unroll
        for (int mt = 0; mt < 2; mt++)
#pragma unroll
            for (int nt = 0; nt < 4; nt++)
                acc[mt][nt][0] = acc[mt][nt][1] = acc[mt][nt][2] = acc[mt][nt][3] = 0.f;
#pragma unroll
        for (int kt = 0; kt < 16; kt++) {
            int k0 = kt * 8;
            uint32_t a[2][4], b[4][2];
#pragma unroll
            for (int mt = 0; mt < 2; mt++) {
                int rb = m0 + mt * 16 + gr;
                a[mt][0] = As[rb * LDH_M + k0 + gc];
                a[mt][1] = As[(rb + 8) * LDH_M + k0 + gc];
                a[mt][2] = As[rb * LDH_M + k0 + gc + 4];
                a[mt][3] = As[(rb + 8) * LDH_M + k0 + gc + 4];
            }
#pragma unroll
            for (int nt = 0; nt < 4; nt++) {
                int cb = n0 + nt * 8 + gr;
                b[nt][0] = Ws[(k0 + gc) * LDW2_M + cb];
                b[nt][1] = Ws[(k0 + gc + 4) * LDW2_M + cb];
            }
#pragma unroll
            for (int mt = 0; mt < 2; mt++)
#pragma unroll
                for (int nt = 0; nt < 4; nt++)
                    mma_tf32(acc[mt][nt], a[mt], b[nt]);
        }
        // epilogue2: +bm1 + residual, store h and feats
#pragma unroll
        for (int mt = 0; mt < 2; mt++) {
            int r  = row0 + m0 + mt * 16 + gr;
            int r8 = r + 8;
#pragma unroll
            for (int nt = 0; nt < 4; nt++) {
                int c = n0 + nt * 8 + 2 * gc;
                float b0v = bm1[c], b1v = bm1[c + 1];
                if (r < nrows) {
                    float2 prev = *(const float2*)(h + (size_t)r * 64 + c);
                    float2 o = make_float2(acc[mt][nt][0] + b0v + prev.x,
                                           acc[mt][nt][1] + b1v + prev.y);
                    *(float2*)(h + (size_t)r * 64 + c) = o;
                    *(float2*)(feats + (size_t)r * FSTR + foff + c) = o;
                }
                if (r8 < nrows) {
                    float2 prev = *(const float2*)(h + (size_t)r8 * 64 + c);
                    float2 o = make_float2(acc[mt][nt][2] + b0v + prev.x,
                                           acc[mt][nt][3] + b1v + prev.y);
                    *(float2*)(h + (size_t)r8 * 64 + c) = o;
                    *(float2*)(feats + (size_t)r8 * FSTR + foff + c) = o;
                }
            }
        }
    }
}

// ---------------- edge attention logits (warp per edge) ----------------
__global__ __launch_bounds__(256) void edge_attn_k(
    const float* __restrict__ hni, const float* __restrict__ hnj,
    const float* __restrict__ table, const float* __restrict__ crcrp,
    const float* __restrict__ attn,
    const float* __restrict__ att_rc, const float* __restrict__ att_rp,
    const int* __restrict__ src, const int* __restrict__ dst,
    const int* __restrict__ etype, const int* __restrict__ rid,
    float* __restrict__ e_out)
{
    __shared__ float sC[640], sAttn[128];
    for (int i = threadIdx.x; i < 640; i += 256) sC[i] = crcrp[i];
    for (int i = threadIdx.x; i < 128; i += 256) sAttn[i] = attn[i];
    __syncthreads();
    int edge = blockIdx.x * 8 + (threadIdx.x >> 5);
    if (edge >= EE) return;
    int lane = threadIdx.x & 31;
    int s = src[edge], d = dst[edge];
    int tr = etype[edge] * 31 + rid[edge];
    float a0 = att_rc[edge * 2], a1 = att_rc[edge * 2 + 1];
    float p0 = att_rp[edge * 3], p1 = att_rp[edge * 3 + 1], p2 = att_rp[edge * 3 + 2];
    int c4 = lane * 4;
    float4 fi = *(const float4*)(hni + (size_t)s * 128 + c4);
    float4 fj = *(const float4*)(hnj + (size_t)d * 128 + c4);
    float4 ft = *(const float4*)(table + (size_t)tr * 128 + c4);
    float fiv[4] = {fi.x, fi.y, fi.z, fi.w};
    float fjv[4] = {fj.x, fj.y, fj.z, fj.w};
    float ftv[4] = {ft.x, ft.y, ft.z, ft.w};
    float acc = 0.f;
#pragma unroll
    for (int j = 0; j < 4; j++) {
        int c = c4 + j;
        float x = fiv[j] + fjv[j] + ftv[j]
                + a0 * sC[c]       + a1 * sC[128 + c]
                + p0 * sC[256 + c] + p1 * sC[384 + c] + p2 * sC[512 + c];
        x = (x >= 0.f) ? x : 0.2f * x;
        acc += x * sAttn[c];
    }
    acc += __shfl_xor_sync(0xffffffffu, acc, 8);
    acc += __shfl_xor_sync(0xffffffffu, acc, 4);
    acc += __shfl_xor_sync(0xffffffffu, acc, 2);
    acc += __shfl_xor_sync(0xffffffffu, acc, 1);
    if ((lane & 15) == 0) e_out[(size_t)edge * 2 + (lane >> 4)] = acc;
}

// ---------------- segment softmax + aggregation (warp per dst node) ----------
__global__ __launch_bounds__(256) void softmax_agg_k(
    const float* __restrict__ e_log, const int* __restrict__ rowptr,
    const int* __restrict__ eidx, const int* __restrict__ src,
    const float* __restrict__ hnode, float* __restrict__ hatt)
{
    int warp = threadIdx.x >> 5, lane = threadIdx.x & 31;
    int node = blockIdx.x * 8 + warp;
    if (node >= NN) return;
    int i0 = rowptr[node], i1 = rowptr[node + 1];
    float4 acc = make_float4(0.f, 0.f, 0.f, 0.f);
    if (i1 > i0) {
        float m0 = -1e30f, m1 = -1e30f, s0 = 0.f, s1 = 0.f;
        for (int i = i0 + lane; i < i1; i += 32) {
            int idx = eidx[i];
            float2 ev = *(const float2*)(e_log + (size_t)idx * 2);
            float n0 = fmaxf(m0, ev.x);
            s0 = s0 * __expf(m0 - n0) + __expf(ev.x - n0);
            m0 = n0;
            float n1 = fmaxf(m1, ev.y);
            s1 = s1 * __expf(m1 - n1) + __expf(ev.y - n1);
            m1 = n1;
        }
#pragma unroll
        for (int o = 16; o; o >>= 1) {
            float mo0 = __shfl_xor_sync(0xffffffffu, m0, o);
            float so0 = __shfl_xor_sync(0xffffffffu, s0, o);
            float mn0 = fmaxf(m0, mo0);
            s0 = s0 * __expf(m0 - mn0) + so0 * __expf(mo0 - mn0);
            m0 = mn0;
            float mo1 = __shfl_xor_sync(0xffffffffu, m1, o);
            float so1 = __shfl_xor_sync(0xffffffffu, s1, o);
            float mn1 = fmaxf(m1, mo1);
            s1 = s1 * __expf(m1 - mn1) + so1 * __expf(mo1 - mn1);
            m1 = mn1;
        }
        int head = lane >> 4;
        float mh   = head ? m1 : m0;
        float invh = 1.f / ((head ? s1 : s0) + 1e-9f);
        int c4 = lane * 4;
        int idx = eidx[i0];
        for (int i = i0; i < i1; i++) {
            int idx_n = (i + 1 < i1) ? eidx[i + 1] : 0;
            int sn = src[idx];
            float el = e_log[(size_t)idx * 2 + head];
            float4 v = *(const float4*)(hnode + (size_t)sn * 128 + c4);
            float alpha = __expf(el - mh) * invh;
            acc.x += alpha * v.x; acc.y += alpha * v.y;
            acc.z += alpha * v.z; acc.w += alpha * v.w;
            idx = idx_n;
        }
    }
    *(float4*)(hatt + (size_t)node * 128 + lane * 4) = acc;
}

// ---------------- graph max pooling (2-stage) + output assembly --------------
__global__ void pool_part_k(const float* __restrict__ feats, float* __restrict__ part) {
    int b = blockIdx.x, fc = blockIdx.y, sp = blockIdx.z;
    int fl = threadIdx.x & 63;
    int f  = fc * 64 + fl;
    int grp = threadIdx.x >> 6;
    int n0 = sp * PS, n1 = n0 + PS;
    if (n1 > NPG) n1 = NPG;
    float m = -1e30f;
    if (f < 266) {
        const float* base = feats + (size_t)b * NPG * FSTR;
        for (int n = n0 + grp; n < n1; n += 4)
            m = fmaxf(m, base[(size_t)n * FSTR + f]);
    }
    __shared__ float sm[256];
    sm[threadIdx.x] = m;
    __syncthreads();
    if (grp == 0) {
        m = fmaxf(fmaxf(sm[threadIdx.x], sm[threadIdx.x + 64]),
                  fmaxf(sm[threadIdx.x + 128], sm[threadIdx.x + 192]));
        part[((b * 5 + fc) * NSPLIT + sp) * 64 + fl] = m;
    }
}
__global__ void pool_reduce_k(const float* __restrict__ part, float* __restrict__ gmax) {
    int b = blockIdx.x, fc = blockIdx.y, t = threadIdx.x;   // block 64
    float m = -1e30f;
#pragma unroll
    for (int sp = 0; sp < NSPLIT; sp++)
        m = fmaxf(m, part[((b * 5 + fc) * NSPLIT + sp) * 64 + t]);
    int f = fc * 64 + t;
    if (f < 266) gmax[b * FSTR + f] = m;
}

__global__ void write_out_k(const float* __restrict__ feats,
                            const float* __restrict__ gmax,
                            float* __restrict__ out) {
    long long idx = (long long)blockIdx.x * 256 + threadIdx.x;
    const long long total = (long long)NB * NPG * 532;
    if (idx >= total) return;
    int c = (int)(idx % 532);
    long long bn = idx / 532;
    int b = (int)(bn / NPG);
    int cl = (c < 266) ? c : (c - 266);
    int ci = (cl < 10) ? (256 + cl) : (cl - 10);
    out[idx] = (c < 266) ? feats[bn * FSTR + ci] : gmax[b * FSTR + ci];
}

// ---------------- host launcher ----------------
extern "C" void kernel_launch(void* const* d_in, const int* in_sizes, int n_in,
                              void* d_out, int out_size)
{
    const float* feat      = (const float*)d_in[0];
    const float* att_rc    = (const float*)d_in[1];
    const float* att_rp    = (const float*)d_in[2];
    const float* etype_emb = (const float*)d_in[3];
    const float* rid_emb   = (const float*)d_in[4];
    const float* rc_W      = (const float*)d_in[5];
    const float* rc_b      = (const float*)d_in[6];
    const float* rp_W      = (const float*)d_in[7];
    const float* rp_b      = (const float*)d_in[8];
    const float* fe_W0     = (const float*)d_in[9];
    const float* fe_b0     = (const float*)d_in[10];
    const float* fe_W1     = (const float*)d_in[11];
    const float* fe_b1     = (const float*)d_in[12];
    const float* W_ni      = (const float*)d_in[13];
    const float* W_nj      = (const float*)d_in[14];
    const float* W_fij     = (const float*)d_in[15];
    const float* W_node    = (const float*)d_in[16];
    const float* attn      = (const float*)d_in[17];
    const float* egat_bias = (const float*)d_in[18];
    const float* Wm0       = (const float*)d_in[19];
    const float* bm0       = (const float*)d_in[20];
    const float* Wm1       = (const float*)d_in[21];
    const float* bm1       = (const float*)d_in[22];
    const int*   src       = (const int*)d_in[23];
    const int*   dst       = (const int*)d_in[24];
    const int*   etype     = (const int*)d_in[25];
    const int*   rid       = (const int*)d_in[26];
    float* out = (float*)d_out;

    float *p_h, *p_hni, *p_hnj, *p_hnode, *p_hatt, *p_feats, *p_e;
    float *p_table, *p_crcrp, *p_gmax, *p_pool;
    int *p_deg, *p_rowptr, *p_cursor, *p_eidx, *p_bsum;
    cudaGetSymbolAddress((void**)&p_h,      g_h);
    cudaGetSymbolAddress((void**)&p_hni,    g_hni);
    cudaGetSymbolAddress((void**)&p_hnj,    g_hnj);
    cudaGetSymbolAddress((void**)&p_hnode,  g_hnode);
    cudaGetSymbolAddress((void**)&p_hatt,   g_hatt);
    cudaGetSymbolAddress((void**)&p_feats,  g_feats);
    cudaGetSymbolAddress((void**)&p_e,      g_e);
    cudaGetSymbolAddress((void**)&p_table,  g_table);
    cudaGetSymbolAddress((void**)&p_crcrp,  g_crcrp);
    cudaGetSymbolAddress((void**)&p_gmax,   g_gmax);
    cudaGetSymbolAddress((void**)&p_pool,   g_pool);
    cudaGetSymbolAddress((void**)&p_deg,    g_deg);
    cudaGetSymbolAddress((void**)&p_rowptr, g_rowptr);
    cudaGetSymbolAddress((void**)&p_cursor, g_cursor);
    cudaGetSymbolAddress((void**)&p_eidx,   g_eidx);
    cudaGetSymbolAddress((void**)&p_bsum,   g_bsum);

    const int SH_PROJ = (128 * LDA_P + 64 * LDW_P) * 4;    // ~68.6 KB
    const int SH_MLP  = (128 * LDH_M * 2) * 4;             // ~135 KB
    cudaFuncSetAttribute((const void*)proj3_k,
                         cudaFuncAttributeMaxDynamicSharedMemorySize, SH_PROJ);
    cudaFuncSetAttribute((const void*)mlp_fused_k,
                         cudaFuncAttributeMaxDynamicSharedMemorySize, SH_MLP);

    const int GRID_T = (NN + 127) / 128;    // 391 (tf32 tiles)
    const int GRID_E = (EE + 255) / 256;    // 1954
    const int NBLK_SCAN = (NN + 255) / 256; // 196

    // 1) feature encoder
    fe_mlp_k<<<(NN + 255) / 256, 256>>>(feat, fe_W0, fe_b0, fe_W1, fe_b1, p_h, p_feats);

    // 2) CSR by dst (parallel scan)
    zero_int_k<<<NBLK_SCAN, 256>>>(p_deg, NN);
    hist_k<<<GRID_E, 256>>>(dst, p_deg);
    scan_partial_k<<<NBLK_SCAN, 256>>>(p_deg, p_bsum);
    scan_bsum_k<<<1, 256>>>(p_bsum, NBLK_SCAN);
    scan_final_k<<<NBLK_SCAN, 256>>>(p_deg, p_bsum, p_rowptr, p_cursor);
    scatter_k<<<GRID_E, 256>>>(dst, p_cursor, p_eidx);

    // 3) EGAT layers
    for (int l = 0; l < 3; l++) {
        precompute_fij_k<<<222, 128>>>(etype_emb, rid_emb, rc_W, rp_W, rc_b, rp_b,
                                       W_fij + l * 64 * 128, egat_bias + l * 128,
                                       p_table, p_crcrp);
        proj3_k<<<dim3(GRID_T, 3), 256, SH_PROJ>>>(
            p_h, W_ni + l * 64 * 128, W_nj + l * 64 * 128, W_node + l * 64 * 128,
            p_hni, p_hnj, p_hnode, NN);

        edge_attn_k<<<EE / 8, 256>>>(p_hni, p_hnj, p_table, p_crcrp,
                                     attn + l * 128, att_rc, att_rp,
                                     src, dst, etype, rid, p_e);

        softmax_agg_k<<<NN / 8, 256>>>(p_e, p_rowptr, p_eidx, src, p_hnode, p_hatt);

        mlp_fused_k<<<GRID_T, 256, SH_MLP>>>(
            p_hatt, Wm0 + l * 128 * 128, bm0 + l * 128,
            Wm1 + l * 128 * 64, bm1 + l * 64,
            p_h, p_feats, 64 * (l + 1), NN);
    }

    // 4) pooling (2-stage) + output
    pool_part_k<<<dim3(NB, 5, NSPLIT), 256>>>(p_feats, p_pool);
    pool_reduce_k<<<dim3(NB, 5), 64>>>(p_pool, p_gmax);
    long long total = (long long)NB * NPG * 532;
    write_out_k<<<(int)((total + 255) / 256), 256>>>(p_feats, p_gmax, out);
}

// round 16
// speedup vs baseline: 1.7831x; 1.2762x over previous
#include <cuda_runtime.h>
#include <cuda_bf16.h>
#include <cstdint>
#include <cstddef>

// ---------------- problem constants ----------------
#define NN     50000
#define EE     500000
#define NPG    6250
#define NB     8
#define FSTR   272
#define NSPLIT 13
#define PS     481
// internal feats layout per node: [h0(64) h1(64) h2(64) h3(64) feat(10) pad(6)]

// ---------------- device scratch ----------------
__device__ __align__(16) float g_h     [NN * 64];
__device__ __align__(16) float g_hni   [NN * 128];
__device__ __align__(16) float g_hnj   [NN * 128];
__device__ __align__(16) float g_hnode [NN * 128];
__device__ __align__(16) float g_hatt  [NN * 128];
__device__ __align__(16) float g_feats [NN * FSTR];
__device__ int   g_deg   [NN];
__device__ int   g_rowptr[NN + 1];
__device__ int   g_cursor[NN];
__device__ int   g_bsum  [256];
__device__ __align__(16) unsigned int g_edata[(size_t)EE * 8];  // CSR-ordered edge records
__device__ __align__(16) float g_table [217 * 128];
__device__ __align__(16) float g_crcrp [5 * 128];
__device__ __align__(16) float g_gmax  [NB * FSTR];
__device__ __align__(16) float g_pool  [NB * 5 * NSPLIT * 64];

// ---------------- tf32 helpers ----------------
__device__ __forceinline__ uint32_t f2tf(float x) {
    uint32_t r;
    asm("cvt.rna.tf32.f32 %0, %1;" : "=r"(r) : "f"(x));
    return r;
}
__device__ __forceinline__ uint4 f4tf(float4 v) {
    return make_uint4(f2tf(v.x), f2tf(v.y), f2tf(v.z), f2tf(v.w));
}
__device__ __forceinline__ void mma_tf32(float c[4], const uint32_t a[4], const uint32_t b[2]) {
    asm volatile(
        "mma.sync.aligned.m16n8k8.row.col.f32.tf32.tf32.f32 "
        "{%0,%1,%2,%3}, {%4,%5,%6,%7}, {%8,%9}, {%0,%1,%2,%3};"
        : "+f"(c[0]), "+f"(c[1]), "+f"(c[2]), "+f"(c[3])
        : "r"(a[0]), "r"(a[1]), "r"(a[2]), "r"(a[3]), "r"(b[0]), "r"(b[1]));
}

// ---------------- feature-encoder MLP (feat -> h0) ----------------
__global__ __launch_bounds__(256) void fe_mlp_k(
    const float* __restrict__ feat, const float* __restrict__ W0,
    const float* __restrict__ b0,   const float* __restrict__ W1,
    const float* __restrict__ b1,   float* __restrict__ h,
    float* __restrict__ feats)
{
    __shared__ float sW0[640], sb0[64], sW1[4096], sb1[64];
    int tid = threadIdx.x;
    for (int i = tid; i < 640;  i += 256) sW0[i] = W0[i];
    for (int i = tid; i < 4096; i += 256) sW1[i] = W1[i];
    if (tid < 64) { sb0[tid] = b0[tid]; sb1[tid] = b1[tid]; }
    __syncthreads();
    int n = blockIdx.x * 256 + tid;
    if (n >= NN) return;
    float f[10];
#pragma unroll
    for (int i = 0; i < 10; i++) {
        f[i] = feat[n * 10 + i];
        feats[(size_t)n * FSTR + 256 + i] = f[i];
    }
    float hid[64];
#pragma unroll
    for (int c = 0; c < 64; c++) {
        float s = sb0[c];
#pragma unroll
        for (int k = 0; k < 10; k++) s += f[k] * sW0[k * 64 + c];
        hid[c] = fmaxf(s, 0.f);
    }
    for (int c = 0; c < 64; c++) {
        float s = sb1[c];
#pragma unroll
        for (int k = 0; k < 64; k++) s += hid[k] * sW1[k * 64 + c];
        h[(size_t)n * 64 + c] = s;
        feats[(size_t)n * FSTR + c] = s;
    }
}

// ---------------- CSR build ----------------
__global__ void zero_int_k(int* p, int n) {
    int i = blockIdx.x * 256 + threadIdx.x;
    if (i < n) p[i] = 0;
}
__global__ void hist_k(const int* __restrict__ dst, int* deg) {
    int e = blockIdx.x * 256 + threadIdx.x;
    if (e < EE) atomicAdd(&deg[dst[e]], 1);
}
__global__ void scan_partial_k(const int* __restrict__ deg, int* bsum) {
    __shared__ int s[256];
    int i = blockIdx.x * 256 + threadIdx.x;
    s[threadIdx.x] = (i < NN) ? deg[i] : 0;
    __syncthreads();
#pragma unroll
    for (int o = 128; o; o >>= 1) {
        if (threadIdx.x < o) s[threadIdx.x] += s[threadIdx.x + o];
        __syncthreads();
    }
    if (threadIdx.x == 0) bsum[blockIdx.x] = s[0];
}
__global__ void scan_bsum_k(int* bsum, int nb) {
    __shared__ int s[256];
    int t = threadIdx.x;
    int v = (t < nb) ? bsum[t] : 0;
    s[t] = v;
    __syncthreads();
#pragma unroll
    for (int o = 1; o < 256; o <<= 1) {
        int x = (t >= o) ? s[t - o] : 0;
        __syncthreads();
        s[t] += x;
        __syncthreads();
    }
    if (t < nb) bsum[t] = s[t] - v;   // exclusive
}
__global__ void scan_final_k(const int* __restrict__ deg, const int* __restrict__ bsum,
                             int* rowptr, int* cursor) {
    __shared__ int s[256];
    int i = blockIdx.x * 256 + threadIdx.x;
    int v = (i < NN) ? deg[i] : 0;
    s[threadIdx.x] = v;
    __syncthreads();
#pragma unroll
    for (int o = 1; o < 256; o <<= 1) {
        int x = (threadIdx.x >= o) ? s[threadIdx.x - o] : 0;
        __syncthreads();
        s[threadIdx.x] += x;
        __syncthreads();
    }
    if (i < NN) {
        int off = bsum[blockIdx.x] + s[threadIdx.x] - v;
        rowptr[i] = off;
        cursor[i] = off;
    }
    if (i == NN - 1) rowptr[NN] = EE;
}
// scatter: also packs per-edge record (CSR order): [src, tr, a0, a1, p0, p1, p2, 0]
__global__ void scatter_k(const int* __restrict__ dst, const int* __restrict__ src,
                          const int* __restrict__ etype, const int* __restrict__ rid,
                          const float* __restrict__ att_rc, const float* __restrict__ att_rp,
                          int* cursor, unsigned int* __restrict__ edata) {
    int e = blockIdx.x * 256 + threadIdx.x;
    if (e < EE) {
        int pos = atomicAdd(&cursor[dst[e]], 1);
        uint4 r0, r1;
        r0.x = (unsigned int)src[e];
        r0.y = (unsigned int)(etype[e] * 31 + rid[e]);
        r0.z = __float_as_uint(att_rc[e * 2]);
        r0.w = __float_as_uint(att_rc[e * 2 + 1]);
        r1.x = __float_as_uint(att_rp[e * 3]);
        r1.y = __float_as_uint(att_rp[e * 3 + 1]);
        r1.z = __float_as_uint(att_rp[e * 3 + 2]);
        r1.w = 0u;
        *(uint4*)(edata + (size_t)pos * 8)     = r0;
        *(uint4*)(edata + (size_t)pos * 8 + 4) = r1;
    }
}

// ---------------- per-layer f_fij precompute ----------------
__global__ void precompute_fij_k(
    const float* __restrict__ etype_emb, const float* __restrict__ rid_emb,
    const float* __restrict__ rc_W, const float* __restrict__ rp_W,
    const float* __restrict__ rc_b, const float* __restrict__ rp_b,
    const float* __restrict__ Wf,   const float* __restrict__ ebias,
    float* __restrict__ table, float* __restrict__ crcrp)
{
    int row = blockIdx.x;         // 0..221
    int c   = threadIdx.x;        // 0..127
    __shared__ float v[64];
    if (threadIdx.x < 64) {
        int k = threadIdx.x;
        float val;
        if (row < 217) {
            int et = row / 31, r = row % 31;
            val = etype_emb[et * 64 + k] + rid_emb[r * 64 + k] + rc_b[k] + rp_b[k];
        } else if (row < 219) {
            val = rc_W[(row - 217) * 64 + k];
        } else {
            val = rp_W[(row - 219) * 64 + k];
        }
        v[k] = val;
    }
    __syncthreads();
    float s = 0.f;
#pragma unroll
    for (int k = 0; k < 64; k++) s += v[k] * Wf[k * 128 + c];
    if (row < 217) table[row * 128 + c] = s + ebias[c];
    else           crcrp[(row - 217) * 128 + c] = s;
}

// ---------------- tf32 3-way projection GEMM: [128,64] tile @ [64,128] ------
#define LDA_P 68
#define LDW_P 132
__global__ __launch_bounds__(256) void proj3_k(
    const float* __restrict__ A,
    const float* __restrict__ W0, const float* __restrict__ W1, const float* __restrict__ W2,
    float* __restrict__ C0, float* __restrict__ C1, float* __restrict__ C2,
    int nrows)
{
    const float* W = (blockIdx.y == 0) ? W0 : (blockIdx.y == 1) ? W1 : W2;
    float*       C = (blockIdx.y == 0) ? C0 : (blockIdx.y == 1) ? C1 : C2;
    extern __shared__ uint32_t smu[];
    uint32_t* As = smu;                 // [128][LDA_P]
    uint32_t* Ws = smu + 128 * LDA_P;   // [64][LDW_P]
    int tid  = threadIdx.x;
    int row0 = blockIdx.x * 128;
#pragma unroll
    for (int i = 0; i < 8; i++) {
        int idx = tid + i * 256;
        int r = idx >> 4, c4 = idx & 15;
        float4 v = make_float4(0.f, 0.f, 0.f, 0.f);
        if (row0 + r < nrows) v = *(const float4*)(A + (size_t)(row0 + r) * 64 + c4 * 4);
        *(uint4*)(As + r * LDA_P + c4 * 4) = f4tf(v);
    }
#pragma unroll
    for (int i = 0; i < 8; i++) {
        int idx = tid + i * 256;
        int r = idx >> 5, c4 = idx & 31;
        *(uint4*)(Ws + r * LDW_P + c4 * 4) = f4tf(*(const float4*)(W + idx * 4));
    }
    __syncthreads();
    int w = tid >> 5, lane = tid & 31;
    int gr = lane >> 2, gc = lane & 3;
    int m0 = (w & 3) * 32, n0 = (w >> 2) * 64;
    float acc[2][8][4];
#pragma unroll
    for (int mt = 0; mt < 2; mt++)
#pragma unroll
        for (int nt = 0; nt < 8; nt++)
            acc[mt][nt][0] = acc[mt][nt][1] = acc[mt][nt][2] = acc[mt][nt][3] = 0.f;
#pragma unroll
    for (int kt = 0; kt < 8; kt++) {
        int k0 = kt * 8;
        uint32_t a[2][4], b[8][2];
#pragma unroll
        for (int mt = 0; mt < 2; mt++) {
            int rb = m0 + mt * 16 + gr;
            a[mt][0] = As[rb * LDA_P + k0 + gc];
            a[mt][1] = As[(rb + 8) * LDA_P + k0 + gc];
            a[mt][2] = As[rb * LDA_P + k0 + gc + 4];
            a[mt][3] = As[(rb + 8) * LDA_P + k0 + gc + 4];
        }
#pragma unroll
        for (int nt = 0; nt < 8; nt++) {
            int cb = n0 + nt * 8 + gr;
            b[nt][0] = Ws[(k0 + gc) * LDW_P + cb];
            b[nt][1] = Ws[(k0 + gc + 4) * LDW_P + cb];
        }
#pragma unroll
        for (int mt = 0; mt < 2; mt++)
#pragma unroll
            for (int nt = 0; nt < 8; nt++)
                mma_tf32(acc[mt][nt], a[mt], b[nt]);
    }
#pragma unroll
    for (int mt = 0; mt < 2; mt++) {
        int r  = row0 + m0 + mt * 16 + gr;
        int r8 = r + 8;
#pragma unroll
        for (int nt = 0; nt < 8; nt++) {
            int c = n0 + nt * 8 + 2 * gc;
            if (r < nrows)
                *(float2*)(C + (size_t)r * 128 + c)  = make_float2(acc[mt][nt][0], acc[mt][nt][1]);
            if (r8 < nrows)
                *(float2*)(C + (size_t)r8 * 128 + c) = make_float2(acc[mt][nt][2], acc[mt][nt][3]);
        }
    }
}

// ---------------- tf32 fused node MLP: h = relu(hatt@Wm0+bm0)@Wm1+bm1 + h ---
#define LDH_M 132
#define LDW2_M 68
__global__ __launch_bounds__(256) void mlp_fused_k(
    const float* __restrict__ hatt,
    const float* __restrict__ Wm0, const float* __restrict__ bm0,
    const float* __restrict__ Wm1, const float* __restrict__ bm1,
    float* __restrict__ h, float* __restrict__ feats, int foff, int nrows)
{
    extern __shared__ uint32_t smu[];
    uint32_t* As = smu;                 // [128][LDH_M]
    uint32_t* Ws = smu + 128 * LDH_M;
    int tid  = threadIdx.x;
    int row0 = blockIdx.x * 128;
#pragma unroll
    for (int i = 0; i < 16; i++) {
        int idx = tid + i * 256;
        int r = idx >> 5, c4 = idx & 31;
        float4 v = make_float4(0.f, 0.f, 0.f, 0.f);
        if (row0 + r < nrows) v = *(const float4*)(hatt + (size_t)(row0 + r) * 128 + c4 * 4);
        *(uint4*)(As + r * LDH_M + c4 * 4) = f4tf(v);
    }
#pragma unroll
    for (int i = 0; i < 16; i++) {
        int idx = tid + i * 256;
        int r = idx >> 5, c4 = idx & 31;
        *(uint4*)(Ws + r * LDH_M + c4 * 4) = f4tf(*(const float4*)(Wm0 + idx * 4));
    }
    __syncthreads();
    int w = tid >> 5, lane = tid & 31;
    int gr = lane >> 2, gc = lane & 3;
    int m0 = (w & 3) * 32;
    {
        int n0 = (w >> 2) * 64;
        float acc[2][8][4];
#pragma unroll
        for (int mt = 0; mt < 2; mt++)
#pragma unroll
            for (int nt = 0; nt < 8; nt++)
                acc[mt][nt][0] = acc[mt][nt][1] = acc[mt][nt][2] = acc[mt][nt][3] = 0.f;
#pragma unroll
        for (int kt = 0; kt < 16; kt++) {
            int k0 = kt * 8;
            uint32_t a[2][4], b[8][2];
#pragma unroll
            for (int mt = 0; mt < 2; mt++) {
                int rb = m0 + mt * 16 + gr;
                a[mt][0] = As[rb * LDH_M + k0 + gc];
                a[mt][1] = As[(rb + 8) * LDH_M + k0 + gc];
                a[mt][2] = As[rb * LDH_M + k0 + gc + 4];
                a[mt][3] = As[(rb + 8) * LDH_M + k0 + gc + 4];
            }
#pragma unroll
            for (int nt = 0; nt < 8; nt++) {
                int cb = n0 + nt * 8 + gr;
                b[nt][0] = Ws[(k0 + gc) * LDH_M + cb];
                b[nt][1] = Ws[(k0 + gc + 4) * LDH_M + cb];
            }
#pragma unroll
            for (int mt = 0; mt < 2; mt++)
#pragma unroll
                for (int nt = 0; nt < 8; nt++)
                    mma_tf32(acc[mt][nt], a[mt], b[nt]);
        }
        __syncthreads();
#pragma unroll
        for (int mt = 0; mt < 2; mt++) {
            int rb  = m0 + mt * 16 + gr;
#pragma unroll
            for (int nt = 0; nt < 8; nt++) {
                int c = n0 + nt * 8 + 2 * gc;
                float b0v = bm0[c], b1v = bm0[c + 1];
                As[rb * LDH_M + c]           = f2tf(fmaxf(acc[mt][nt][0] + b0v, 0.f));
                As[rb * LDH_M + c + 1]       = f2tf(fmaxf(acc[mt][nt][1] + b1v, 0.f));
                As[(rb + 8) * LDH_M + c]     = f2tf(fmaxf(acc[mt][nt][2] + b0v, 0.f));
                As[(rb + 8) * LDH_M + c + 1] = f2tf(fmaxf(acc[mt][nt][3] + b1v, 0.f));
            }
        }
    }
#pragma unroll
    for (int i = 0; i < 8; i++) {
        int idx = tid + i * 256;
        int r = idx >> 4, c4 = idx & 15;
        *(uint4*)(Ws + r * LDW2_M + c4 * 4) = f4tf(*(const float4*)(Wm1 + idx * 4));
    }
    __syncthreads();
    {
        int n0 = (w >> 2) * 32;
        float acc[2][4][4];
#pragma unroll
        for (int mt = 0; mt < 2; mt++)
#pragma unroll
            for (int nt = 0; nt < 4; nt++)
                acc[mt][nt][0] = acc[mt][nt][1] = acc[mt][nt][2] = acc[mt][nt][3] = 0.f;
#pragma unroll
        for (int kt = 0; kt < 16; kt++) {
            int k0 = kt * 8;
            uint32_t a[2][4], b[4][2];
#pragma unroll
            for (int mt = 0; mt < 2; mt++) {
                int rb = m0 + mt * 16 + gr;
                a[mt][0] = As[rb * LDH_M + k0 + gc];
                a[mt][1] = As[(rb + 8) * LDH_M + k0 + gc];
                a[mt][2] = As[rb * LDH_M + k0 + gc + 4];
                a[mt][3] = As[(rb + 8) * LDH_M + k0 + gc + 4];
            }
#pragma unroll
            for (int nt = 0; nt < 4; nt++) {
                int cb = n0 + nt * 8 + gr;
                b[nt][0] = Ws[(k0 + gc) * LDW2_M + cb];
                b[nt][1] = Ws[(k0 + gc + 4) * LDW2_M + cb];
            }
#pragma unroll
            for (int mt = 0; mt < 2; mt++)
#pragma unroll
                for (int nt = 0; nt < 4; nt++)
                    mma_tf32(acc[mt][nt], a[mt], b[nt]);
        }
#pragma unroll
        for (int mt = 0; mt < 2; mt++) {
            int r  = row0 + m0 + mt * 16 + gr;
            int r8 = r + 8;
#pragma unroll
            for (int nt = 0; nt < 4; nt++) {
                int c = n0 + nt * 8 + 2 * gc;
                float b0v = bm1[c], b1v = bm1[c + 1];
                if (r < nrows) {
                    float2 prev = *(const float2*)(h + (size_t)r * 64 + c);
                    float2 o = make_float2(acc[mt][nt][0] + b0v + prev.x,
                                           acc[mt][nt][1] + b1v + prev.y);
                    *(float2*)(h + (size_t)r * 64 + c) = o;
                    *(float2*)(feats + (size_t)r * FSTR + foff + c) = o;
                }
                if (r8 < nrows) {
                    float2 prev = *(const float2*)(h + (size_t)r8 * 64 + c);
                    float2 o = make_float2(acc[mt][nt][2] + b0v + prev.x,
                                           acc[mt][nt][3] + b1v + prev.y);
                    *(float2*)(h + (size_t)r8 * 64 + c) = o;
                    *(float2*)(feats + (size_t)r8 * FSTR + foff + c) = o;
                }
            }
        }
    }
}

// ---------------- fused edge attention + online softmax + aggregation -------
// warp per dst node. Per edge: logit from hni[src]+hnj[dst]+table[tr]+rank-5,
// flash-style rescaled accumulation of hnode[src]. One pass over edges.
__global__ __launch_bounds__(256) void attn_agg_k(
    const float* __restrict__ hni, const float* __restrict__ hnj,
    const float* __restrict__ hnode,
    const float* __restrict__ table, const float* __restrict__ crcrp,
    const float* __restrict__ attn,
    const int* __restrict__ rowptr, const unsigned int* __restrict__ edata,
    float* __restrict__ hatt)
{
    __shared__ float sC[640], sAttn[128];
    for (int i = threadIdx.x; i < 640; i += 256) sC[i] = crcrp[i];
    for (int i = threadIdx.x; i < 128; i += 256) sAttn[i] = attn[i];
    __syncthreads();
    int warp = threadIdx.x >> 5, lane = threadIdx.x & 31;
    int node = blockIdx.x * 8 + warp;
    if (node >= NN) return;
    int i0 = rowptr[node], i1 = rowptr[node + 1];
    int c4 = lane * 4;
    float4 acc = make_float4(0.f, 0.f, 0.f, 0.f);
    if (i1 > i0) {
        // per-lane channel constants
        float at0 = sAttn[c4], at1 = sAttn[c4 + 1], at2 = sAttn[c4 + 2], at3 = sAttn[c4 + 3];
        float4 fj = *(const float4*)(hnj + (size_t)node * 128 + c4);   // once per node
        float m = -1e30f, s = 0.f;
        unsigned int rec = edata[(size_t)i0 * 8 + (lane & 7)];
        for (int i = i0; i < i1; i++) {
            // broadcast record fields (words 0..6 live in lanes 0..6)
            int   sn = (int)__shfl_sync(0xffffffffu, rec, 0);
            int   tr = (int)__shfl_sync(0xffffffffu, rec, 1);
            float a0 = __uint_as_float(__shfl_sync(0xffffffffu, rec, 2));
            float a1 = __uint_as_float(__shfl_sync(0xffffffffu, rec, 3));
            float p0 = __uint_as_float(__shfl_sync(0xffffffffu, rec, 4));
            float p1 = __uint_as_float(__shfl_sync(0xffffffffu, rec, 5));
            float p2 = __uint_as_float(__shfl_sync(0xffffffffu, rec, 6));
            // issue gathers early
            float4 fi = *(const float4*)(hni   + (size_t)sn * 128 + c4);
            float4 v  = *(const float4*)(hnode + (size_t)sn * 128 + c4);
            float4 ft = *(const float4*)(table + (size_t)tr * 128 + c4);
            // prefetch next record
            if (i + 1 < i1) rec = edata[(size_t)(i + 1) * 8 + (lane & 7)];
            // per-channel logit contribution
            float x0 = fi.x + fj.x + ft.x + a0 * sC[c4]     + a1 * sC[128 + c4]
                     + p0 * sC[256 + c4]     + p1 * sC[384 + c4]     + p2 * sC[512 + c4];
            float x1 = fi.y + fj.y + ft.y + a0 * sC[c4 + 1] + a1 * sC[129 + c4]
                     + p0 * sC[257 + c4]     + p1 * sC[385 + c4]     + p2 * sC[513 + c4];
            float x2 = fi.z + fj.z + ft.z + a0 * sC[c4 + 2] + a1 * sC[130 + c4]
                     + p0 * sC[258 + c4]     + p1 * sC[386 + c4]     + p2 * sC[514 + c4];
            float x3 = fi.w + fj.w + ft.w + a0 * sC[c4 + 3] + a1 * sC[131 + c4]
                     + p0 * sC[259 + c4]     + p1 * sC[387 + c4]     + p2 * sC[515 + c4];
            x0 = (x0 >= 0.f) ? x0 : 0.2f * x0;
            x1 = (x1 >= 0.f) ? x1 : 0.2f * x1;
            x2 = (x2 >= 0.f) ? x2 : 0.2f * x2;
            x3 = (x3 >= 0.f) ? x3 : 0.2f * x3;
            float part = x0 * at0 + x1 * at1 + x2 * at2 + x3 * at3;
            // half-warp reduce -> e (head 0 in lanes 0-15, head 1 in lanes 16-31)
            part += __shfl_xor_sync(0xffffffffu, part, 8);
            part += __shfl_xor_sync(0xffffffffu, part, 4);
            part += __shfl_xor_sync(0xffffffffu, part, 2);
            part += __shfl_xor_sync(0xffffffffu, part, 1);
            float e = part;
            // online softmax update (per half-warp)
            float n  = fmaxf(m, e);
            float sc = __expf(m - n);
            float p  = __expf(e - n);
            s = s * sc + p;
            acc.x = acc.x * sc + p * v.x;
            acc.y = acc.y * sc + p * v.y;
            acc.z = acc.z * sc + p * v.z;
            acc.w = acc.w * sc + p * v.w;
            m = n;
        }
        float inv = 1.f / (s + 1e-9f);
        acc.x *= inv; acc.y *= inv; acc.z *= inv; acc.w *= inv;
    }
    *(float4*)(hatt + (size_t)node * 128 + c4) = acc;
}

// ---------------- graph max pooling (2-stage) + output assembly --------------
__global__ void pool_part_k(const float* __restrict__ feats, float* __restrict__ part) {
    int b = blockIdx.x, fc = blockIdx.y, sp = blockIdx.z;
    int fl = threadIdx.x & 63;
    int f  = fc * 64 + fl;
    int grp = threadIdx.x >> 6;
    int n0 = sp * PS, n1 = n0 + PS;
    if (n1 > NPG) n1 = NPG;
    float m = -1e30f;
    if (f < 266) {
        const float* base = feats + (size_t)b * NPG * FSTR;
        for (int n = n0 + grp; n < n1; n += 4)
            m = fmaxf(m, base[(size_t)n * FSTR + f]);
    }
    __shared__ float sm[256];
    sm[threadIdx.x] = m;
    __syncthreads();
    if (grp == 0) {
        m = fmaxf(fmaxf(sm[threadIdx.x], sm[threadIdx.x + 64]),
                  fmaxf(sm[threadIdx.x + 128], sm[threadIdx.x + 192]));
        part[((b * 5 + fc) * NSPLIT + sp) * 64 + fl] = m;
    }
}
__global__ void pool_reduce_k(const float* __restrict__ part, float* __restrict__ gmax) {
    int b = blockIdx.x, fc = blockIdx.y, t = threadIdx.x;   // block 64
    float m = -1e30f;
#pragma unroll
    for (int sp = 0; sp < NSPLIT; sp++)
        m = fmaxf(m, part[((b * 5 + fc) * NSPLIT + sp) * 64 + t]);
    int f = fc * 64 + t;
    if (f < 266) gmax[b * FSTR + f] = m;
}

__global__ void write_out_k(const float* __restrict__ feats,
                            const float* __restrict__ gmax,
                            float* __restrict__ out) {
    long long idx = (long long)blockIdx.x * 256 + threadIdx.x;
    const long long total = (long long)NB * NPG * 532;
    if (idx >= total) return;
    int c = (int)(idx % 532);
    long long bn = idx / 532;
    int b = (int)(bn / NPG);
    int cl = (c < 266) ? c : (c - 266);
    int ci = (cl < 10) ? (256 + cl) : (cl - 10);
    out[idx] = (c < 266) ? feats[bn * FSTR + ci] : gmax[b * FSTR + ci];
}

// ---------------- host launcher ----------------
extern "C" void kernel_launch(void* const* d_in, const int* in_sizes, int n_in,
                              void* d_out, int out_size)
{
    const float* feat      = (const float*)d_in[0];
    const float* att_rc    = (const float*)d_in[1];
    const float* att_rp    = (const float*)d_in[2];
    const float* etype_emb = (const float*)d_in[3];
    const float* rid_emb   = (const float*)d_in[4];
    const float* rc_W      = (const float*)d_in[5];
    const float* rc_b      = (const float*)d_in[6];
    const float* rp_W      = (const float*)d_in[7];
    const float* rp_b      = (const float*)d_in[8];
    const float* fe_W0     = (const float*)d_in[9];
    const float* fe_b0     = (const float*)d_in[10];
    const float* fe_W1     = (const float*)d_in[11];
    const float* fe_b1     = (const float*)d_in[12];
    const float* W_ni      = (const float*)d_in[13];
    const float* W_nj      = (const float*)d_in[14];
    const float* W_fij     = (const float*)d_in[15];
    const float* W_node    = (const float*)d_in[16];
    const float* attn      = (const float*)d_in[17];
    const float* egat_bias = (const float*)d_in[18];
    const float* Wm0       = (const float*)d_in[19];
    const float* bm0       = (const float*)d_in[20];
    const float* Wm1       = (const float*)d_in[21];
    const float* bm1       = (const float*)d_in[22];
    const int*   src       = (const int*)d_in[23];
    const int*   dst       = (const int*)d_in[24];
    const int*   etype     = (const int*)d_in[25];
    const int*   rid       = (const int*)d_in[26];
    float* out = (float*)d_out;

    float *p_h, *p_hni, *p_hnj, *p_hnode, *p_hatt, *p_feats;
    float *p_table, *p_crcrp, *p_gmax, *p_pool;
    int *p_deg, *p_rowptr, *p_cursor, *p_bsum;
    unsigned int* p_edata;
    cudaGetSymbolAddress((void**)&p_h,      g_h);
    cudaGetSymbolAddress((void**)&p_hni,    g_hni);
    cudaGetSymbolAddress((void**)&p_hnj,    g_hnj);
    cudaGetSymbolAddress((void**)&p_hnode,  g_hnode);
    cudaGetSymbolAddress((void**)&p_hatt,   g_hatt);
    cudaGetSymbolAddress((void**)&p_feats,  g_feats);
    cudaGetSymbolAddress((void**)&p_table,  g_table);
    cudaGetSymbolAddress((void**)&p_crcrp,  g_crcrp);
    cudaGetSymbolAddress((void**)&p_gmax,   g_gmax);
    cudaGetSymbolAddress((void**)&p_pool,   g_pool);
    cudaGetSymbolAddress((void**)&p_deg,    g_deg);
    cudaGetSymbolAddress((void**)&p_rowptr, g_rowptr);
    cudaGetSymbolAddress((void**)&p_cursor, g_cursor);
    cudaGetSymbolAddress((void**)&p_bsum,   g_bsum);
    cudaGetSymbolAddress((void**)&p_edata,  g_edata);

    const int SH_PROJ = (128 * LDA_P + 64 * LDW_P) * 4;    // ~68.6 KB
    const int SH_MLP  = (128 * LDH_M * 2) * 4;             // ~135 KB
    cudaFuncSetAttribute((const void*)proj3_k,
                         cudaFuncAttributeMaxDynamicSharedMemorySize, SH_PROJ);
    cudaFuncSetAttribute((const void*)mlp_fused_k,
                         cudaFuncAttributeMaxDynamicSharedMemorySize, SH_MLP);

    const int GRID_T = (NN + 127) / 128;    // 391 (tf32 tiles)
    const int GRID_E = (EE + 255) / 256;    // 1954
    const int NBLK_SCAN = (NN + 255) / 256; // 196

    // 1) feature encoder
    fe_mlp_k<<<(NN + 255) / 256, 256>>>(feat, fe_W0, fe_b0, fe_W1, fe_b1, p_h, p_feats);

    // 2) CSR by dst (parallel scan) + packed edge records
    zero_int_k<<<NBLK_SCAN, 256>>>(p_deg, NN);
    hist_k<<<GRID_E, 256>>>(dst, p_deg);
    scan_partial_k<<<NBLK_SCAN, 256>>>(p_deg, p_bsum);
    scan_bsum_k<<<1, 256>>>(p_bsum, NBLK_SCAN);
    scan_final_k<<<NBLK_SCAN, 256>>>(p_deg, p_bsum, p_rowptr, p_cursor);
    scatter_k<<<GRID_E, 256>>>(dst, src, etype, rid, att_rc, att_rp, p_cursor, p_edata);

    // 3) EGAT layers
    for (int l = 0; l < 3; l++) {
        precompute_fij_k<<<222, 128>>>(etype_emb, rid_emb, rc_W, rp_W, rc_b, rp_b,
                                       W_fij + l * 64 * 128, egat_bias + l * 128,
                                       p_table, p_crcrp);
        proj3_k<<<dim3(GRID_T, 3), 256, SH_PROJ>>>(
            p_h, W_ni + l * 64 * 128, W_nj + l * 64 * 128, W_node + l * 64 * 128,
            p_hni, p_hnj, p_hnode, NN);

        attn_agg_k<<<NN / 8, 256>>>(p_hni, p_hnj, p_hnode, p_table, p_crcrp,
                                    attn + l * 128, p_rowptr, p_edata, p_hatt);

        mlp_fused_k<<<GRID_T, 256, SH_MLP>>>(
            p_hatt, Wm0 + l * 128 * 128, bm0 + l * 128,
            Wm1 + l * 128 * 64, bm1 + l * 64,
            p_h, p_feats, 64 * (l + 1), NN);
    }

    // 4) pooling (2-stage) + output
    pool_part_k<<<dim3(NB, 5, NSPLIT), 256>>>(p_feats, p_pool);
    pool_reduce_k<<<dim3(NB, 5), 64>>>(p_pool, p_gmax);
    long long total = (long long)NB * NPG * 532;
    write_out_k<<<(int)((total + 255) / 256), 256>>>(p_feats, p_gmax, out);
}